// round 11
// baseline (speedup 1.0000x reference)
#include <cuda_runtime.h>
#include <cuda.h>
#include <cuda_bf16.h>
#include <cstdint>

// ---------------------------------------------------------------------------
// Arch feature gate: tcgen05/TMEM are "a"-target-only. Non-"a" passes compile
// the SIMT fallback instead; exactly one GEMM kernel is active per pass.
// ---------------------------------------------------------------------------
#if defined(__CUDA_ARCH__) && (defined(__CUDA_ARCH_FEAT_SM103_ALL) || defined(__CUDA_ARCH_FEAT_SM100_ALL))
#define HAS_TC 1
#else
#define HAS_TC 0
#endif

// Problem constants
#define NB 4
#define C  256
#define HR 60
#define WR 60
#define M  3600          // HR*WR
#define MP 3712          // padded to 29*128
#define GS 8
#define HH 480
#define WW 480

#define BM 128
#define BN 128
#define BK 8
#define GB 29            // tiles per GEMM dim
#define NT 29            // A tiles per strip (persistent loop)
#define NH (2 * NT)      // K=128 half-tiles
#define NPOSB 1800

// idesc kind::f16: dtype=F32(1<<4), atype=BF16(1<<7), btype=BF16(1<<10),
// N/8 << 17, M/16 << 24  ->  M=128, N=128
#define MMA_IDESC 0x8200490u

// smem layout (dynamic, 1024-aligned): A slots 0..3 @ s*32768 (32KB each),
// B @ 131072 (64KB). Total 192KB.
#define A_SLOT(s)  ((uint32_t)(s) * 32768u)
#define B_OFF      131072u

// __device__ scratch (no allocation allowed)
__device__ __align__(16) __nv_bfloat16 d_D1t[(size_t)NB * MP * C];  // [n][m][c] bf16
__device__ __align__(16) __nv_bfloat16 d_D2t[(size_t)NB * MP * C];
__device__ float d_D1p[NB * C * MP];                                // fp32 fallback
__device__ float d_D2p[NB * C * MP];
__device__ float d_vm[NB * MP];
__device__ float d_partA[NB * GB];
__device__ float d_partB[NPOSB];

// ---------------------------------------------------------------------------
// Helpers
// ---------------------------------------------------------------------------
__device__ __forceinline__ uint32_t smem_u32(const void* p) {
    uint32_t a;
    asm("{ .reg .u64 t; cvta.to.shared.u64 t, %1; cvt.u32.u64 %0, t; }" : "=r"(a) : "l"(p));
    return a;
}

#if HAS_TC
__device__ __forceinline__ uint32_t elect_one() {
    uint32_t p;
    asm volatile("{ .reg .pred p; elect.sync _|p, 0xFFFFFFFF; selp.b32 %0, 1, 0, p; }" : "=r"(p));
    return p;
}
static __device__ __forceinline__ uint64_t make_desc(uint32_t addr) {
    // SW128, version=1(Blackwell), SBO=64, LBO=1
    const uint64_t base = (uint64_t(2) << 61) | (uint64_t(1) << 46)
                        | (uint64_t(64) << 32) | (uint64_t(1) << 16);
    return base | ((uint64_t)(addr >> 4) & 0x3FFF);
}
__device__ __forceinline__ void mma_f16_ss_cg1(uint32_t d_tmem, uint64_t a_desc,
                                               uint64_t b_desc, uint32_t idesc,
                                               uint32_t enable) {
    asm volatile(
        "{\n\t.reg .pred p;\n\t"
        "setp.ne.u32 p, %4, 0;\n\t"
        "tcgen05.mma.cta_group::1.kind::f16 [%0], %1, %2, %3, {%5, %5, %5, %5}, p;\n\t}"
        :: "r"(d_tmem), "l"(a_desc), "l"(b_desc), "r"(idesc), "r"(enable), "r"(0u)
        : "memory");
}
__device__ __forceinline__ void mbar_wait(uint32_t mbar, uint32_t parity) {
    uint32_t done;
    asm volatile(
        "{\n\t.reg .pred p;\n\t"
        "mbarrier.try_wait.parity.acquire.cta.shared::cta.b64 p, [%1], %2;\n\t"
        "selp.b32 %0, 1, 0, p;\n\t}"
        : "=r"(done) : "r"(mbar), "r"(parity) : "memory");
    if (!done) {
        asm volatile(
            "{\n\t.reg .pred P1;\n\t"
            "WL_%=:\n\t"
            "mbarrier.try_wait.parity.acquire.cta.shared::cta.b64 P1, [%0], %1, 0x989680;\n\t"
            "@P1 bra.uni WD_%=;\n\t"
            "bra.uni WL_%=;\n\t"
            "WD_%=:\n\t}"
            :: "r"(mbar), "r"(parity) : "memory");
    }
}
__device__ __forceinline__ void mbar_arrive(uint32_t mbar) {
    asm volatile("mbarrier.arrive.release.cta.shared::cta.b64 _, [%0];"
                 :: "r"(mbar) : "memory");
}
__device__ __forceinline__ void mbar_expect_tx(uint32_t mbar, uint32_t bytes) {
    asm volatile("mbarrier.arrive.expect_tx.shared.b64 _, [%0], %1;"
                 :: "r"(mbar), "r"(bytes) : "memory");
}
__device__ __forceinline__ void tma3d(uint32_t dst, const CUtensorMap* tmap,
                                      int x, int y, int z, uint32_t mbar) {
    asm volatile(
        "cp.async.bulk.tensor.3d.shared::cta.global.tile.mbarrier::complete_tx::bytes "
        "[%0], [%1, {%2, %3, %4}], [%5];"
        :: "r"(dst), "l"((uint64_t)tmap), "r"(x), "r"(y), "r"(z), "r"(mbar)
        : "memory");
}

#define LDTM_X32(dr, addr)                                                     \
    asm volatile(                                                              \
        "tcgen05.ld.sync.aligned.32x32b.x32.b32 "                              \
        "{%0, %1, %2, %3, %4, %5, %6, %7, "                                    \
        " %8, %9, %10, %11, %12, %13, %14, %15, "                              \
        " %16, %17, %18, %19, %20, %21, %22, %23, "                            \
        " %24, %25, %26, %27, %28, %29, %30, %31}, [%32];"                     \
        : "=r"((dr)[0]),  "=r"((dr)[1]),  "=r"((dr)[2]),  "=r"((dr)[3]),       \
          "=r"((dr)[4]),  "=r"((dr)[5]),  "=r"((dr)[6]),  "=r"((dr)[7]),       \
          "=r"((dr)[8]),  "=r"((dr)[9]),  "=r"((dr)[10]), "=r"((dr)[11]),      \
          "=r"((dr)[12]), "=r"((dr)[13]), "=r"((dr)[14]), "=r"((dr)[15]),      \
          "=r"((dr)[16]), "=r"((dr)[17]), "=r"((dr)[18]), "=r"((dr)[19]),      \
          "=r"((dr)[20]), "=r"((dr)[21]), "=r"((dr)[22]), "=r"((dr)[23]),      \
          "=r"((dr)[24]), "=r"((dr)[25]), "=r"((dr)[26]), "=r"((dr)[27]),      \
          "=r"((dr)[28]), "=r"((dr)[29]), "=r"((dr)[30]), "=r"((dr)[31])       \
        : "r"(addr))

// Epilogue: this warp reads 64 columns [c0, c0+64) of its 32-lane
// subpartition. Hinge via max(d, 0.2); constant part folded out at the end.
__device__ __forceinline__ void epi64(uint32_t tsrc, const float* vmv, float& local) {
    uint32_t dr[64];
    LDTM_X32(dr,      tsrc);
    LDTM_X32(dr + 32, tsrc + 32);
    asm volatile("tcgen05.wait::ld.sync.aligned;" ::: "memory");
    float a0 = 0.f, a1 = 0.f, a2 = 0.f, a3 = 0.f;
    #pragma unroll
    for (int k = 0; k < 64; k += 4) {
        a0 = fmaf(vmv[k + 0], fmaxf(__uint_as_float(dr[k + 0]), 0.2f), a0);
        a1 = fmaf(vmv[k + 1], fmaxf(__uint_as_float(dr[k + 1]), 0.2f), a1);
        a2 = fmaf(vmv[k + 2], fmaxf(__uint_as_float(dr[k + 2]), 0.2f), a2);
        a3 = fmaf(vmv[k + 3], fmaxf(__uint_as_float(dr[k + 3]), 0.2f), a3);
    }
    local += (a0 + a1) + (a2 + a3);
}
#endif

// ---------------------------------------------------------------------------
// Transpose + pad + bf16 convert: [n][c][m] f32 -> [n][m][c] bf16.
// Non-"a" targets also write zero-padded fp32 copies for the SIMT fallback.
// ---------------------------------------------------------------------------
__global__ void transpose_kernel(const float* __restrict__ d1,
                                 const float* __restrict__ d2) {
    __shared__ float t1[32][33];
    __shared__ float t2[32][33];
    int m0 = blockIdx.x * 32, c0 = blockIdx.y * 32, n = blockIdx.z;
    int tx = threadIdx.x, ty = threadIdx.y;   // 32 x 8

    #pragma unroll
    for (int i = 0; i < 4; i++) {
        int c = c0 + ty + i * 8, m = m0 + tx;
        float v1 = 0.f, v2 = 0.f;
        if (m < M) {
            size_t idx = ((size_t)n * C + c) * M + m;
            v1 = d1[idx]; v2 = d2[idx];
        }
        t1[ty + i * 8][tx] = v1;
        t2[ty + i * 8][tx] = v2;
#if !HAS_TC
        size_t o = ((size_t)n * C + c) * MP + m;
        d_D1p[o] = v1;
        d_D2p[o] = v2;
#endif
    }
    __syncthreads();
    #pragma unroll
    for (int i = 0; i < 4; i++) {
        int m = m0 + ty + i * 8, c = c0 + tx;
        if (m < MP) {
            size_t o = ((size_t)n * MP + m) * C + c;
            d_D1t[o] = __float2bfloat16(t1[tx][ty + i * 8]);
            d_D2t[o] = __float2bfloat16(t2[tx][ty + i * 8]);
        }
    }
}

// ---------------------------------------------------------------------------
// vm[n, i, j] = prod of 8x8 block of vis_mask1; padded entries are 0.
// ---------------------------------------------------------------------------
__global__ void vm_kernel(const float* __restrict__ vis) {
    int idx = blockIdx.x * blockDim.x + threadIdx.x;
    if (idx >= NB * MP) return;
    int mp = idx % MP;
    int n  = idx / MP;
    float p = 0.f;
    if (mp < M) {
        int i = mp / WR, j = mp % WR;
        p = 1.f;
        const float* base = vis + n * HH * WW + (i * GS) * WW + j * GS;
        #pragma unroll
        for (int a = 0; a < GS; a++)
            #pragma unroll
            for (int b = 0; b < GS; b++)
                p *= base[a * WW + b];
    }
    d_vm[idx] = p;
}

// ---------------------------------------------------------------------------
// Warp-specialized persistent-strip tcgen05 GEMM with TMA loads.
// Grid (29, 1, 4), 288 threads = 8 pure-epilogue warps + 1 MMA+TMA warp.
// B strip (full K, 64KB) TMA'd once; A streamed as K=128 half-tiles through
// a 4-slot ring (32KB each) via TMA issued by the MMA warp's elected thread
// (expect_tx barriers). Commit-per-half signals slot reuse + tile done.
// mbarriers: load[4] (cnt1+tx), half[4] (cnt1, commit), epi[2] (cnt256), B (cnt1+tx).
// ---------------------------------------------------------------------------
__global__ __launch_bounds__(288, 1) void gemm_tc_kernel(
    const __grid_constant__ CUtensorMap tmapA,
    const __grid_constant__ CUtensorMap tmapB) {
#if HAS_TC
    extern __shared__ char dyn_sm[];
    __shared__ uint32_t s_tmem[1];
    __shared__ __align__(8) unsigned long long s_mbar[11]; // load[4] half[4] epi[2] B
    __shared__ float s_red[8];

    const int n   = blockIdx.z;
    const int xs  = blockIdx.x;
    const int tid = threadIdx.x;
    const int wid = tid >> 5, lid = tid & 31;

    uint32_t raw  = smem_u32(dyn_sm);
    uint32_t base = (raw + 1023u) & ~1023u;

    if (wid == 8) {
        asm volatile("tcgen05.alloc.cta_group::1.sync.aligned.shared::cta.b32 [%0], %1;"
                     :: "r"(smem_u32(s_tmem)), "r"(256u) : "memory");
        asm volatile("tcgen05.relinquish_alloc_permit.cta_group::1.sync.aligned;");
    }
    if (tid == 0) {
        #pragma unroll
        for (int k = 0; k < 8; k++)
            asm volatile("mbarrier.init.shared.b64 [%0], %1;"
                         :: "r"(smem_u32(&s_mbar[k])), "r"(1u) : "memory");
        #pragma unroll
        for (int k = 8; k < 10; k++)
            asm volatile("mbarrier.init.shared.b64 [%0], %1;"
                         :: "r"(smem_u32(&s_mbar[k])), "r"(256u) : "memory");
        asm volatile("mbarrier.init.shared.b64 [%0], %1;"
                     :: "r"(smem_u32(&s_mbar[10])), "r"(1u) : "memory");
    }
    __syncthreads();
    const uint32_t tmem = s_tmem[0];
    uint32_t mb_load[4], mb_half[4], mb_epi[2], mb_B;
    #pragma unroll
    for (int k = 0; k < 4; k++) { mb_load[k] = smem_u32(&s_mbar[k]); mb_half[k] = smem_u32(&s_mbar[4 + k]); }
    mb_epi[0] = smem_u32(&s_mbar[8]); mb_epi[1] = smem_u32(&s_mbar[9]);
    mb_B = smem_u32(&s_mbar[10]);

    if (wid < 8) {
        // ---------------- pure epilogue warps (256 threads) ----------------
        const int c0 = (wid >= 4) ? 64 : 0;
        float vmv[64];
        float sum_vm = 0.f;
        {
            const float* vmb = d_vm + n * MP + xs * BN + c0;
            #pragma unroll
            for (int k = 0; k < 64; k++) { vmv[k] = vmb[k]; sum_vm += vmb[k]; }
        }

        float local = 0.f;
        #pragma unroll 1
        for (int tt = 0; tt < NT; tt++) {
            const int s = (tt & 1) ? 3 : 1;           // odd half h=2tt+1 slot
            mbar_wait(mb_half[s], (uint32_t)((tt >> 1) & 1));
            asm volatile("tcgen05.fence::after_thread_sync;" ::: "memory");
            epi64(tmem + (tt & 1) * 128 + c0, vmv, local);
            mbar_arrive(mb_epi[tt & 1]);              // tmem[tt&1] consumed
        }

        local -= 0.2f * (float)NT * sum_vm;           // fold out hinge constant

        #pragma unroll
        for (int o = 16; o > 0; o >>= 1)
            local += __shfl_down_sync(0xffffffffu, local, o);
        if (lid == 0) s_red[wid] = local;
    } else {
        // ---------------- MMA + TMA producer warp ----------------
        const bool leader = elect_one() != 0;

        // TMA for half h (2 chunks of 64 cols = 32KB) into slot h&3
        auto tma_half = [&](int h) {
            const int t = h >> 1, s = h & 3, ko = (h & 1) * 128;
            mbar_expect_tx(mb_load[s], 32768u);
            tma3d(base + A_SLOT(s),          &tmapA, ko,      t * 128, n, mb_load[s]);
            tma3d(base + A_SLOT(s) + 16384u, &tmapA, ko + 64, t * 128, n, mb_load[s]);
        };

        if (leader) {
            mbar_expect_tx(mb_B, 65536u);
            #pragma unroll
            for (int cc = 0; cc < 4; cc++)
                tma3d(base + B_OFF + cc * 16384u, &tmapB, cc * 64, xs * 128, n, mb_B);
            tma_half(0);
            tma_half(1);
            tma_half(2);
        }
        mbar_wait(mb_B, 0u);

        int pl[4] = {0, 0, 0, 0};
        int pe[2] = {0, 0};

        #pragma unroll 1
        for (int h = 0; h < NH; h++) {
            const int s = h & 3, t = h >> 1;
            mbar_wait(mb_load[s], (uint32_t)(pl[s] & 1));
            pl[s]++;
            if (!(h & 1) && t >= 2) {                 // tmem[t&1] free of t-2 reads
                mbar_wait(mb_epi[t & 1], (uint32_t)(pe[t & 1] & 1));
                pe[t & 1]++;
            }
            if (leader) {
                const uint32_t dt = tmem + (t & 1) * 128;
                #pragma unroll
                for (int cc = 0; cc < 2; cc++) {
                    uint64_t ad = make_desc(base + A_SLOT(s) + cc * 16384u);
                    uint64_t bd = make_desc(base + B_OFF + ((h & 1) * 2 + cc) * 16384u);
                    #pragma unroll
                    for (int ks = 0; ks < 4; ks++)
                        mma_f16_ss_cg1(dt, ad + ks * 2, bd + ks * 2, MMA_IDESC,
                                       (uint32_t)((h & 1) | cc | ks));
                }
                asm volatile(
                    "tcgen05.commit.cta_group::1.mbarrier::arrive::one.shared::cluster.b64 [%0];"
                    :: "r"(mb_half[s]) : "memory");
            }
            const int h2 = h + 3;
            if (h2 < NH) {
                const int s2 = h2 & 3;
                if (h2 >= 4)                           // slot free <=> MMA(h2-4) done
                    mbar_wait(mb_half[s2], (uint32_t)(((h2 - 4) >> 2) & 1));
                if (leader) tma_half(h2);
            }
        }
    }

    __syncthreads();
    if (tid == 0) {
        float t = 0.f;
        #pragma unroll
        for (int w = 0; w < 8; w++) t += s_red[w];
        d_partA[n * GB + xs] = t;
    }
    if (wid == 8) {
        asm volatile("tcgen05.dealloc.cta_group::1.sync.aligned.b32 %0, %1;"
                     :: "r"(tmem), "r"(256u));
    }
#endif
}

// ---------------------------------------------------------------------------
// Fallback SIMT fp32 GEMM, persistent strips (active only WITHOUT tcgen05).
// Grid (29, 1, 4): CTA owns B strip, loops over 29 A tiles.
// ---------------------------------------------------------------------------
__global__ __launch_bounds__(256, 1) void gemm_simt_kernel() {
#if !HAS_TC
    int n = blockIdx.z, xs = blockIdx.x;
    const float* Bb = d_D2p + n * C * MP + xs * BN;

    __shared__ float As[2][BK][BM];
    __shared__ float Bs[2][BK][BN];

    int tid  = threadIdx.x;
    int tx   = tid & 15;
    int ty2  = tid >> 4;
    int lrow = tid >> 5;
    int lcol = (tid & 31) << 2;

    float vmv[8];
    #pragma unroll
    for (int j = 0; j < 8; j++)
        vmv[j] = d_vm[n * MP + xs * BN + tx * 8 + j];

    float total = 0.f;

    #pragma unroll 1
    for (int ty = 0; ty < GB; ty++) {
        const float* Ab = d_D1p + n * C * MP + ty * BM;

        float acc[8][8];
        #pragma unroll
        for (int i = 0; i < 8; i++)
            #pragma unroll
            for (int j = 0; j < 8; j++) acc[i][j] = 0.f;

        *(float4*)&As[0][lrow][lcol] = *(const float4*)&Ab[lrow * MP + lcol];
        *(float4*)&Bs[0][lrow][lcol] = *(const float4*)&Bb[lrow * MP + lcol];
        __syncthreads();

        #pragma unroll 1
        for (int k0 = 0; k0 < C; k0 += BK) {
            int buf = (k0 >> 3) & 1;
            if (k0 + BK < C) {
                *(float4*)&As[buf ^ 1][lrow][lcol] =
                    *(const float4*)&Ab[(k0 + BK + lrow) * MP + lcol];
                *(float4*)&Bs[buf ^ 1][lrow][lcol] =
                    *(const float4*)&Bb[(k0 + BK + lrow) * MP + lcol];
            }
            #pragma unroll
            for (int kk = 0; kk < BK; kk++) {
                float a[8], b[8];
                *(float4*)&a[0] = *(const float4*)&As[buf][kk][ty2 * 8];
                *(float4*)&a[4] = *(const float4*)&As[buf][kk][ty2 * 8 + 4];
                *(float4*)&b[0] = *(const float4*)&Bs[buf][kk][tx * 8];
                *(float4*)&b[4] = *(const float4*)&Bs[buf][kk][tx * 8 + 4];
                #pragma unroll
                for (int i = 0; i < 8; i++)
                    #pragma unroll
                    for (int j = 0; j < 8; j++)
                        acc[i][j] = fmaf(a[i], b[j], acc[i][j]);
            }
            __syncthreads();
        }

        #pragma unroll
        for (int i = 0; i < 8; i++)
            #pragma unroll
            for (int j = 0; j < 8; j++)
                total += vmv[j] * fmaxf(acc[i][j] - 0.2f, 0.f);
    }

    #pragma unroll
    for (int o = 16; o > 0; o >>= 1)
        total += __shfl_down_sync(0xffffffffu, total, o);

    __shared__ float wsum[8];
    if ((tid & 31) == 0) wsum[tid >> 5] = total;
    __syncthreads();
    if (tid == 0) {
        float t = 0.f;
        #pragma unroll
        for (int w = 0; w < 8; w++) t += wsum[w];
        d_partA[n * GB + xs] = t;
    }
#endif
}

// ---------------------------------------------------------------------------
// Positive-pair correction (coalesced bf16 dots on transposed arrays).
// ---------------------------------------------------------------------------
__device__ __forceinline__ float dot8(uint4 a, uint4 b) {
    const __nv_bfloat162* pa = (const __nv_bfloat162*)&a;
    const __nv_bfloat162* pb = (const __nv_bfloat162*)&b;
    float s = 0.f;
    #pragma unroll
    for (int k = 0; k < 4; k++) {
        float2 fa = __bfloat1622float2(pa[k]);
        float2 fb = __bfloat1622float2(pb[k]);
        s += fa.x * fb.x + fa.y * fb.y;
    }
    return s;
}

__global__ void pos_kernel(const float* __restrict__ homo) {
    int warp = threadIdx.x >> 5;
    int lane = threadIdx.x & 31;
    int item = blockIdx.x * 8 + warp;   // 0 .. 14399
    float contrib = 0.f;

    if (item < NB * M) {
        int n  = item / M;
        int ij = item % M;
        int i  = ij / WR, j = ij % WR;
        float x = j * 8 + 4.f, y = i * 8 + 4.f;
        const float* Hm = homo + n * 9;
        float wxh = Hm[0] * x + Hm[1] * y + Hm[2];
        float wyh = Hm[3] * x + Hm[4] * y + Hm[5];
        float wzh = Hm[6] * x + Hm[7] * y + Hm[8];
        float wx = wxh / wzh, wy = wyh / wzh;
        float vmv = d_vm[n * MP + ij];

        const uint4 bvec = ((const uint4*)(d_D2t + ((size_t)n * MP + ij) * C))[lane];

        int hs = (int)floorf((wy - 11.5f) * 0.125f);
        int ws = (int)floorf((wx - 11.5f) * 0.125f);
        for (int hh = hs; hh < hs + 4; hh++) {
            if (hh < 0 || hh >= HR) continue;
            float dy = hh * 8 + 4.f - wy;
            for (int wc = ws; wc < ws + 4; wc++) {
                if (wc < 0 || wc >= WR) continue;
                float dx = wc * 8 + 4.f - wx;
                if (dx * dx + dy * dy <= 56.25f) {   // dist <= 7.5
                    const uint4 avec =
                        ((const uint4*)(d_D1t + ((size_t)n * MP + hh * WR + wc) * C))[lane];
                    float dt = dot8(avec, bvec);
                    #pragma unroll
                    for (int o = 16; o > 0; o >>= 1)
                        dt += __shfl_down_sync(0xffffffffu, dt, o);
                    dt = __shfl_sync(0xffffffffu, dt, 0);
                    if (lane == 0)
                        contrib += vmv * (fmaxf(1.f - dt, 0.f) - fmaxf(dt - 0.2f, 0.f));
                }
            }
        }
    }

    __shared__ float wsh[8];
    if (lane == 0) wsh[warp] = contrib;
    __syncthreads();
    if (threadIdx.x == 0) {
        float t = 0.f;
        #pragma unroll
        for (int w = 0; w < 8; w++) t += wsh[w];
        d_partB[blockIdx.x] = t;
    }
}

// ---------------------------------------------------------------------------
// Final deterministic reduction (both paths write 116 strip partials).
// ---------------------------------------------------------------------------
__global__ void final_kernel(float* __restrict__ out) {
    __shared__ float sh[256];
    int tid = threadIdx.x;

    float s = 0.f;
    for (int k = tid; k < NB * GB; k += 256) s += d_partA[k];
    for (int k = tid; k < NPOSB; k += 256) s += d_partB[k];
    float v = 0.f;
    for (int k = tid; k < NB * MP; k += 256) v += d_vm[k];  // pads are 0

    sh[tid] = s;
    __syncthreads();
    for (int o = 128; o > 0; o >>= 1) {
        if (tid < o) sh[tid] += sh[tid + o];
        __syncthreads();
    }
    float total = sh[0];
    __syncthreads();

    sh[tid] = v;
    __syncthreads();
    for (int o = 128; o > 0; o >>= 1) {
        if (tid < o) sh[tid] += sh[tid + o];
        __syncthreads();
    }
    if (tid == 0)
        out[0] = total / (3600.f * sh[0]);   // LOSS_LAMBDA = 1
}

// ---------------------------------------------------------------------------
// Host: tensormap construction via driver entry point (no -lcuda needed).
// ---------------------------------------------------------------------------
typedef CUresult (*PFN_encodeTiled)(
    CUtensorMap*, CUtensorMapDataType, cuuint32_t, void*,
    const cuuint64_t*, const cuuint64_t*, const cuuint32_t*, const cuuint32_t*,
    CUtensorMapInterleave, CUtensorMapSwizzle, CUtensorMapL2promotion,
    CUtensorMapFloatOOBfill);

static void build_tmap(PFN_encodeTiled enc, CUtensorMap* tm, void* gptr) {
    cuuint64_t dims[3]    = {C, MP, NB};
    cuuint64_t strides[2] = {(cuuint64_t)C * 2, (cuuint64_t)MP * C * 2};
    cuuint32_t box[3]     = {64, 128, 1};
    cuuint32_t es[3]      = {1, 1, 1};
    enc(tm, CU_TENSOR_MAP_DATA_TYPE_BFLOAT16, 3, gptr, dims, strides, box, es,
        CU_TENSOR_MAP_INTERLEAVE_NONE, CU_TENSOR_MAP_SWIZZLE_128B,
        CU_TENSOR_MAP_L2_PROMOTION_L2_128B, CU_TENSOR_MAP_FLOAT_OOB_FILL_NONE);
}

extern "C" void kernel_launch(void* const* d_in, const int* in_sizes, int n_in,
                              void* d_out, int out_size) {
    const float* desc1 = nullptr;
    const float* desc2 = nullptr;
    const float* homo  = nullptr;
    const float* vis   = nullptr;
    for (int k = 0; k < n_in; k++) {
        if (in_sizes[k] == NB * C * M) {
            if (!desc1) desc1 = (const float*)d_in[k];
            else if (!desc2) desc2 = (const float*)d_in[k];
        } else if (in_sizes[k] == NB * 9) {
            homo = (const float*)d_in[k];
        } else if (in_sizes[k] == NB * HH * WW) {
            vis = (const float*)d_in[k];
        }
    }

    // tensormaps for the GEMM TMA loads (host-side only; baked into the graph)
    CUtensorMap tA, tB;
    {
        void* fn = nullptr;
        cudaDriverEntryPointQueryResult qr;
#if CUDART_VERSION >= 12050
        cudaGetDriverEntryPointByVersion("cuTensorMapEncodeTiled", &fn, 12000,
                                         cudaEnableDefault, &qr);
#else
        cudaGetDriverEntryPoint("cuTensorMapEncodeTiled", &fn,
                                cudaEnableDefault, &qr);
#endif
        void* pA = nullptr; void* pB = nullptr;
        cudaGetSymbolAddress(&pA, d_D1t);
        cudaGetSymbolAddress(&pB, d_D2t);
        if (fn) {
            build_tmap((PFN_encodeTiled)fn, &tA, pA);
            build_tmap((PFN_encodeTiled)fn, &tB, pB);
        }
    }

    // Idempotent, capture-safe.
    cudaFuncSetAttribute(gemm_tc_kernel,
                         cudaFuncAttributeMaxDynamicSharedMemorySize, 197632);

    transpose_kernel<<<dim3(116, 8, NB), dim3(32, 8)>>>(desc1, desc2);
    vm_kernel<<<(NB * MP + 255) / 256, 256>>>(vis);
    gemm_tc_kernel<<<dim3(GB, 1, NB), 288, 197632>>>(tA, tB);   // active on "a"
    gemm_simt_kernel<<<dim3(GB, 1, NB), 256>>>();               // active otherwise
    pos_kernel<<<NPOSB, 256>>>(homo);
    final_kernel<<<1, 256>>>((float*)d_out);
}

// round 12
// speedup vs baseline: 1.0483x; 1.0483x over previous
#include <cuda_runtime.h>
#include <cuda.h>
#include <cuda_bf16.h>
#include <cstdint>

// ---------------------------------------------------------------------------
// Arch feature gate: tcgen05/TMEM are "a"-target-only. Non-"a" passes compile
// the SIMT fallback instead; exactly one GEMM kernel is active per pass.
// ---------------------------------------------------------------------------
#if defined(__CUDA_ARCH__) && (defined(__CUDA_ARCH_FEAT_SM103_ALL) || defined(__CUDA_ARCH_FEAT_SM100_ALL))
#define HAS_TC 1
#else
#define HAS_TC 0
#endif

// Problem constants
#define NB 4
#define C  256
#define HR 60
#define WR 60
#define M  3600          // HR*WR
#define MP 3712          // padded to 29*128
#define GS 8
#define HH 480
#define WW 480

#define BM 128
#define BN 128
#define BK 8
#define GB 29            // tiles per GEMM dim
#define NPOSB 1800

// idesc kind::f16: dtype=F32(1<<4), atype=BF16(1<<7), btype=BF16(1<<10),
// N/8 << 17, M/16 << 24  ->  M=128, N=128
#define MMA_IDESC 0x8200490u

// smem layout (dynamic, 1024-aligned): A quarter slots 0..1 @ s*16384 (16KB),
// B @ 32768 (64KB). Total 96KB -> 2 CTAs/SM.
#define A_SLOT(s)  ((uint32_t)(s) * 16384u)
#define B_OFF      32768u

// __device__ scratch (no allocation allowed)
__device__ __align__(16) __nv_bfloat16 d_D1t[(size_t)NB * MP * C];  // [n][m][c] bf16
__device__ __align__(16) __nv_bfloat16 d_D2t[(size_t)NB * MP * C];
__device__ float d_D1p[NB * C * MP];                                // fp32 fallback
__device__ float d_D2p[NB * C * MP];
__device__ float d_vm[NB * MP];
__device__ float d_partA[NB * GB * 2];
__device__ float d_partB[NPOSB];

// ---------------------------------------------------------------------------
// Helpers
// ---------------------------------------------------------------------------
__device__ __forceinline__ uint32_t smem_u32(const void* p) {
    uint32_t a;
    asm("{ .reg .u64 t; cvta.to.shared.u64 t, %1; cvt.u32.u64 %0, t; }" : "=r"(a) : "l"(p));
    return a;
}

#if HAS_TC
__device__ __forceinline__ uint32_t elect_one() {
    uint32_t p;
    asm volatile("{ .reg .pred p; elect.sync _|p, 0xFFFFFFFF; selp.b32 %0, 1, 0, p; }" : "=r"(p));
    return p;
}
static __device__ __forceinline__ uint64_t make_desc(uint32_t addr) {
    // SW128, version=1(Blackwell), SBO=64, LBO=1
    const uint64_t base = (uint64_t(2) << 61) | (uint64_t(1) << 46)
                        | (uint64_t(64) << 32) | (uint64_t(1) << 16);
    return base | ((uint64_t)(addr >> 4) & 0x3FFF);
}
__device__ __forceinline__ void mma_f16_ss_cg1(uint32_t d_tmem, uint64_t a_desc,
                                               uint64_t b_desc, uint32_t idesc,
                                               uint32_t enable) {
    asm volatile(
        "{\n\t.reg .pred p;\n\t"
        "setp.ne.u32 p, %4, 0;\n\t"
        "tcgen05.mma.cta_group::1.kind::f16 [%0], %1, %2, %3, {%5, %5, %5, %5}, p;\n\t}"
        :: "r"(d_tmem), "l"(a_desc), "l"(b_desc), "r"(idesc), "r"(enable), "r"(0u)
        : "memory");
}
__device__ __forceinline__ void mbar_wait(uint32_t mbar, uint32_t parity) {
    uint32_t done;
    asm volatile(
        "{\n\t.reg .pred p;\n\t"
        "mbarrier.try_wait.parity.acquire.cta.shared::cta.b64 p, [%1], %2;\n\t"
        "selp.b32 %0, 1, 0, p;\n\t}"
        : "=r"(done) : "r"(mbar), "r"(parity) : "memory");
    if (!done) {
        asm volatile(
            "{\n\t.reg .pred P1;\n\t"
            "WL_%=:\n\t"
            "mbarrier.try_wait.parity.acquire.cta.shared::cta.b64 P1, [%0], %1, 0x989680;\n\t"
            "@P1 bra.uni WD_%=;\n\t"
            "bra.uni WL_%=;\n\t"
            "WD_%=:\n\t}"
            :: "r"(mbar), "r"(parity) : "memory");
    }
}
__device__ __forceinline__ void mbar_arrive(uint32_t mbar) {
    asm volatile("mbarrier.arrive.release.cta.shared::cta.b64 _, [%0];"
                 :: "r"(mbar) : "memory");
}
__device__ __forceinline__ void mbar_expect_tx(uint32_t mbar, uint32_t bytes) {
    asm volatile("mbarrier.arrive.expect_tx.shared.b64 _, [%0], %1;"
                 :: "r"(mbar), "r"(bytes) : "memory");
}
__device__ __forceinline__ void tma3d(uint32_t dst, const CUtensorMap* tmap,
                                      int x, int y, int z, uint32_t mbar) {
    asm volatile(
        "cp.async.bulk.tensor.3d.shared::cta.global.tile.mbarrier::complete_tx::bytes "
        "[%0], [%1, {%2, %3, %4}], [%5];"
        :: "r"(dst), "l"((uint64_t)tmap), "r"(x), "r"(y), "r"(z), "r"(mbar)
        : "memory");
}

#define LDTM_X32(dr, addr)                                                     \
    asm volatile(                                                              \
        "tcgen05.ld.sync.aligned.32x32b.x32.b32 "                              \
        "{%0, %1, %2, %3, %4, %5, %6, %7, "                                    \
        " %8, %9, %10, %11, %12, %13, %14, %15, "                              \
        " %16, %17, %18, %19, %20, %21, %22, %23, "                            \
        " %24, %25, %26, %27, %28, %29, %30, %31}, [%32];"                     \
        : "=r"((dr)[0]),  "=r"((dr)[1]),  "=r"((dr)[2]),  "=r"((dr)[3]),       \
          "=r"((dr)[4]),  "=r"((dr)[5]),  "=r"((dr)[6]),  "=r"((dr)[7]),       \
          "=r"((dr)[8]),  "=r"((dr)[9]),  "=r"((dr)[10]), "=r"((dr)[11]),      \
          "=r"((dr)[12]), "=r"((dr)[13]), "=r"((dr)[14]), "=r"((dr)[15]),      \
          "=r"((dr)[16]), "=r"((dr)[17]), "=r"((dr)[18]), "=r"((dr)[19]),      \
          "=r"((dr)[20]), "=r"((dr)[21]), "=r"((dr)[22]), "=r"((dr)[23]),      \
          "=r"((dr)[24]), "=r"((dr)[25]), "=r"((dr)[26]), "=r"((dr)[27]),      \
          "=r"((dr)[28]), "=r"((dr)[29]), "=r"((dr)[30]), "=r"((dr)[31])       \
        : "r"(addr))
#endif

// ---------------------------------------------------------------------------
// Transpose + pad + bf16 convert: [n][c][m] f32 -> [n][m][c] bf16.
// Non-"a" targets also write zero-padded fp32 copies for the SIMT fallback.
// ---------------------------------------------------------------------------
__global__ void transpose_kernel(const float* __restrict__ d1,
                                 const float* __restrict__ d2) {
    __shared__ float t1[32][33];
    __shared__ float t2[32][33];
    int m0 = blockIdx.x * 32, c0 = blockIdx.y * 32, n = blockIdx.z;
    int tx = threadIdx.x, ty = threadIdx.y;   // 32 x 8

    #pragma unroll
    for (int i = 0; i < 4; i++) {
        int c = c0 + ty + i * 8, m = m0 + tx;
        float v1 = 0.f, v2 = 0.f;
        if (m < M) {
            size_t idx = ((size_t)n * C + c) * M + m;
            v1 = d1[idx]; v2 = d2[idx];
        }
        t1[ty + i * 8][tx] = v1;
        t2[ty + i * 8][tx] = v2;
#if !HAS_TC
        size_t o = ((size_t)n * C + c) * MP + m;
        d_D1p[o] = v1;
        d_D2p[o] = v2;
#endif
    }
    __syncthreads();
    #pragma unroll
    for (int i = 0; i < 4; i++) {
        int m = m0 + ty + i * 8, c = c0 + tx;
        if (m < MP) {
            size_t o = ((size_t)n * MP + m) * C + c;
            d_D1t[o] = __float2bfloat16(t1[tx][ty + i * 8]);
            d_D2t[o] = __float2bfloat16(t2[tx][ty + i * 8]);
        }
    }
}

// ---------------------------------------------------------------------------
// vm[n, i, j] = prod of 8x8 block of vis_mask1; padded entries are 0.
// ---------------------------------------------------------------------------
__global__ void vm_kernel(const float* __restrict__ vis) {
    int idx = blockIdx.x * blockDim.x + threadIdx.x;
    if (idx >= NB * MP) return;
    int mp = idx % MP;
    int n  = idx / MP;
    float p = 0.f;
    if (mp < M) {
        int i = mp / WR, j = mp % WR;
        p = 1.f;
        const float* base = vis + n * HH * WW + (i * GS) * WW + j * GS;
        #pragma unroll
        for (int a = 0; a < GS; a++)
            #pragma unroll
            for (int b = 0; b < GS; b++)
                p *= base[a * WW + b];
    }
    d_vm[idx] = p;
}

// ---------------------------------------------------------------------------
// Occupancy-2 warp-specialized tcgen05 GEMM with TMA loads.
// Grid (29, 2, 4) = 232 CTAs, 2 per SM (96KB smem, <=113 regs). CTA (xs, ys, n)
// owns B strip xs (full K resident, 64KB) and A tiles [t0, t0+nt) where
// ys=0 -> tiles 0..14, ys=1 -> 15..28. A streamed as K=64 quarters through a
// 2-slot ring (16KB, TMA box 64x128). MMA warp: per quarter wait load ->
// 4 MMAs -> commit to mb_q[slot]; tile-final quarter ALSO commits to
// mb_tile[t&1] (fixes skipped-completion parity); then waits mb_q[slot]
// (exec done) and TMA-prefetches quarter q+2 into the freed slot.
// Epilogue warps: wait mb_tile, 2x (LDTM x32 + hinge, vm via LDS broadcast),
// arrive mb_epi (tmem buffer reuse, double-buffered by tile).
// ---------------------------------------------------------------------------
__global__ __launch_bounds__(288, 2) void gemm_tc_kernel(
    const __grid_constant__ CUtensorMap tmapA,
    const __grid_constant__ CUtensorMap tmapB) {
#if HAS_TC
    extern __shared__ char dyn_sm[];
    __shared__ uint32_t s_tmem[1];
    __shared__ __align__(8) unsigned long long s_mbar[9]; // load[2] q[2] tile[2] epi[2] B
    __shared__ float s_red[8];
    __shared__ float s_vm[BN];

    const int n   = blockIdx.z;
    const int xs  = blockIdx.x;
    const int ys  = blockIdx.y;
    const int tid = threadIdx.x;
    const int wid = tid >> 5, lid = tid & 31;

    const int nt = (ys == 0) ? 15 : 14;       // tiles this CTA
    const int t0 = (ys == 0) ? 0 : 15;        // first global tile
    const int Q  = 4 * nt;                    // quarters

    uint32_t raw  = smem_u32(dyn_sm);
    uint32_t base = (raw + 1023u) & ~1023u;

    if (wid == 8) {
        asm volatile("tcgen05.alloc.cta_group::1.sync.aligned.shared::cta.b32 [%0], %1;"
                     :: "r"(smem_u32(s_tmem)), "r"(256u) : "memory");
        asm volatile("tcgen05.relinquish_alloc_permit.cta_group::1.sync.aligned;");
    }
    if (tid == 0) {
        #pragma unroll
        for (int k = 0; k < 6; k++)   // load[2], q[2], tile[2]: count 1
            asm volatile("mbarrier.init.shared.b64 [%0], %1;"
                         :: "r"(smem_u32(&s_mbar[k])), "r"(1u) : "memory");
        #pragma unroll
        for (int k = 6; k < 8; k++)   // epi[2]: count 256
            asm volatile("mbarrier.init.shared.b64 [%0], %1;"
                         :: "r"(smem_u32(&s_mbar[k])), "r"(256u) : "memory");
        asm volatile("mbarrier.init.shared.b64 [%0], %1;"
                     :: "r"(smem_u32(&s_mbar[8])), "r"(1u) : "memory");  // B
    }
    if (tid < BN) s_vm[tid] = d_vm[n * MP + xs * BN + tid];
    __syncthreads();
    const uint32_t tmem = s_tmem[0];
    uint32_t mb_load[2], mb_q[2], mb_tile[2], mb_epi[2], mb_B;
    #pragma unroll
    for (int k = 0; k < 2; k++) {
        mb_load[k] = smem_u32(&s_mbar[k]);
        mb_q[k]    = smem_u32(&s_mbar[2 + k]);
        mb_tile[k] = smem_u32(&s_mbar[4 + k]);
        mb_epi[k]  = smem_u32(&s_mbar[6 + k]);
    }
    mb_B = smem_u32(&s_mbar[8]);

    if (wid < 8) {
        // ---------------- pure epilogue warps (256 threads) ----------------
        const int c0 = (wid >= 4) ? 64 : 0;
        float sum_vm = 0.f;
        #pragma unroll
        for (int k = 0; k < 64; k++) sum_vm += s_vm[c0 + k];

        float local = 0.f;
        #pragma unroll 1
        for (int tt = 0; tt < nt; tt++) {
            mbar_wait(mb_tile[tt & 1], (uint32_t)((tt >> 1) & 1));
            asm volatile("tcgen05.fence::after_thread_sync;" ::: "memory");
            #pragma unroll
            for (int ch = 0; ch < 2; ch++) {
                uint32_t dr[32];
                LDTM_X32(dr, tmem + (tt & 1) * 128 + c0 + ch * 32);
                asm volatile("tcgen05.wait::ld.sync.aligned;" ::: "memory");
                float a0 = 0.f, a1 = 0.f, a2 = 0.f, a3 = 0.f;
                #pragma unroll
                for (int k = 0; k < 32; k += 4) {
                    a0 = fmaf(s_vm[c0 + ch * 32 + k + 0],
                              fmaxf(__uint_as_float(dr[k + 0]), 0.2f), a0);
                    a1 = fmaf(s_vm[c0 + ch * 32 + k + 1],
                              fmaxf(__uint_as_float(dr[k + 1]), 0.2f), a1);
                    a2 = fmaf(s_vm[c0 + ch * 32 + k + 2],
                              fmaxf(__uint_as_float(dr[k + 2]), 0.2f), a2);
                    a3 = fmaf(s_vm[c0 + ch * 32 + k + 3],
                              fmaxf(__uint_as_float(dr[k + 3]), 0.2f), a3);
                }
                local += (a0 + a1) + (a2 + a3);
            }
            mbar_arrive(mb_epi[tt & 1]);       // tmem[tt&1] consumed
        }

        local -= 0.2f * (float)nt * sum_vm;    // fold out hinge constant

        #pragma unroll
        for (int o = 16; o > 0; o >>= 1)
            local += __shfl_down_sync(0xffffffffu, local, o);
        if (lid == 0) s_red[wid] = local;
    } else {
        // ---------------- MMA + TMA producer warp ----------------
        const bool leader = elect_one() != 0;

        // TMA quarter q into slot q&1: box 64x128 = 16KB, one request.
        auto tma_q = [&](int q) {
            const int s = q & 1, t = q >> 2, qq = q & 3;
            mbar_expect_tx(mb_load[s], 16384u);
            tma3d(base + A_SLOT(s), &tmapA, qq * 64, (t0 + t) * 128, n, mb_load[s]);
        };

        if (leader) {
            mbar_expect_tx(mb_B, 65536u);
            #pragma unroll
            for (int cc = 0; cc < 4; cc++)
                tma3d(base + B_OFF + cc * 16384u, &tmapB, cc * 64, xs * 128, n, mb_B);
            tma_q(0);
            tma_q(1);
        }
        mbar_wait(mb_B, 0u);

        int pl[2] = {0, 0};   // mb_load parities
        int pq[2] = {0, 0};   // mb_q parities
        int pe[2] = {0, 0};   // mb_epi parities

        #pragma unroll 1
        for (int q = 0; q < Q; q++) {
            const int s = q & 1, t = q >> 2, qq = q & 3;
            mbar_wait(mb_load[s], (uint32_t)(pl[s] & 1));
            pl[s]++;
            if (qq == 0 && t >= 2) {           // tmem[t&1] free of tile t-2 reads
                mbar_wait(mb_epi[t & 1], (uint32_t)(pe[t & 1] & 1));
                pe[t & 1]++;
            }
            if (leader) {
                const uint32_t dt = tmem + (t & 1) * 128;
                uint64_t ad = make_desc(base + A_SLOT(s));
                uint64_t bd = make_desc(base + B_OFF + qq * 16384u);
                #pragma unroll
                for (int ks = 0; ks < 4; ks++)
                    mma_f16_ss_cg1(dt, ad + ks * 2, bd + ks * 2, MMA_IDESC,
                                   (uint32_t)(qq | ks));
                asm volatile(
                    "tcgen05.commit.cta_group::1.mbarrier::arrive::one.shared::cluster.b64 [%0];"
                    :: "r"(mb_q[s]) : "memory");
                if (qq == 3)
                    asm volatile(
                        "tcgen05.commit.cta_group::1.mbarrier::arrive::one.shared::cluster.b64 [%0];"
                        :: "r"(mb_tile[t & 1]) : "memory");
            }
            if (q + 2 < Q) {                   // prefetch into slot s once exec(q) done
                mbar_wait(mb_q[s], (uint32_t)(pq[s] & 1));
                pq[s]++;
                if (leader) tma_q(q + 2);
            }
        }
    }

    __syncthreads();
    if (tid == 0) {
        float t = 0.f;
        #pragma unroll
        for (int w = 0; w < 8; w++) t += s_red[w];
        d_partA[(n * GB + xs) * 2 + ys] = t;
    }
    if (wid == 8) {
        asm volatile("tcgen05.dealloc.cta_group::1.sync.aligned.b32 %0, %1;"
                     :: "r"(tmem), "r"(256u));
    }
#endif
}

// ---------------------------------------------------------------------------
// Fallback SIMT fp32 GEMM, persistent strips (active only WITHOUT tcgen05).
// Grid (29, 2, 4): y=0 handles the whole strip, y=1 exits (keeps grids equal).
// ---------------------------------------------------------------------------
__global__ __launch_bounds__(256, 1) void gemm_simt_kernel() {
#if !HAS_TC
    if (blockIdx.y != 0) return;
    int n = blockIdx.z, xs = blockIdx.x;
    const float* Bb = d_D2p + n * C * MP + xs * BN;

    __shared__ float As[2][BK][BM];
    __shared__ float Bs[2][BK][BN];

    int tid  = threadIdx.x;
    int tx   = tid & 15;
    int ty2  = tid >> 4;
    int lrow = tid >> 5;
    int lcol = (tid & 31) << 2;

    float vmv[8];
    #pragma unroll
    for (int j = 0; j < 8; j++)
        vmv[j] = d_vm[n * MP + xs * BN + tx * 8 + j];

    float total = 0.f;

    #pragma unroll 1
    for (int ty = 0; ty < GB; ty++) {
        const float* Ab = d_D1p + n * C * MP + ty * BM;

        float acc[8][8];
        #pragma unroll
        for (int i = 0; i < 8; i++)
            #pragma unroll
            for (int j = 0; j < 8; j++) acc[i][j] = 0.f;

        *(float4*)&As[0][lrow][lcol] = *(const float4*)&Ab[lrow * MP + lcol];
        *(float4*)&Bs[0][lrow][lcol] = *(const float4*)&Bb[lrow * MP + lcol];
        __syncthreads();

        #pragma unroll 1
        for (int k0 = 0; k0 < C; k0 += BK) {
            int buf = (k0 >> 3) & 1;
            if (k0 + BK < C) {
                *(float4*)&As[buf ^ 1][lrow][lcol] =
                    *(const float4*)&Ab[(k0 + BK + lrow) * MP + lcol];
                *(float4*)&Bs[buf ^ 1][lrow][lcol] =
                    *(const float4*)&Bb[(k0 + BK + lrow) * MP + lcol];
            }
            #pragma unroll
            for (int kk = 0; kk < BK; kk++) {
                float a[8], b[8];
                *(float4*)&a[0] = *(const float4*)&As[buf][kk][ty2 * 8];
                *(float4*)&a[4] = *(const float4*)&As[buf][kk][ty2 * 8 + 4];
                *(float4*)&b[0] = *(const float4*)&Bs[buf][kk][tx * 8];
                *(float4*)&b[4] = *(const float4*)&Bs[buf][kk][tx * 8 + 4];
                #pragma unroll
                for (int i = 0; i < 8; i++)
                    #pragma unroll
                    for (int j = 0; j < 8; j++)
                        acc[i][j] = fmaf(a[i], b[j], acc[i][j]);
            }
            __syncthreads();
        }

        #pragma unroll
        for (int i = 0; i < 8; i++)
            #pragma unroll
            for (int j = 0; j < 8; j++)
                total += vmv[j] * fmaxf(acc[i][j] - 0.2f, 0.f);
    }

    #pragma unroll
    for (int o = 16; o > 0; o >>= 1)
        total += __shfl_down_sync(0xffffffffu, total, o);

    __shared__ float wsum[8];
    if ((tid & 31) == 0) wsum[tid >> 5] = total;
    __syncthreads();
    if (tid == 0) {
        float t = 0.f;
        #pragma unroll
        for (int w = 0; w < 8; w++) t += wsum[w];
        d_partA[(n * GB + xs) * 2] = t;
        d_partA[(n * GB + xs) * 2 + 1] = 0.f;
    }
#endif
}

// ---------------------------------------------------------------------------
// Positive-pair correction (coalesced bf16 dots on transposed arrays).
// ---------------------------------------------------------------------------
__device__ __forceinline__ float dot8(uint4 a, uint4 b) {
    const __nv_bfloat162* pa = (const __nv_bfloat162*)&a;
    const __nv_bfloat162* pb = (const __nv_bfloat162*)&b;
    float s = 0.f;
    #pragma unroll
    for (int k = 0; k < 4; k++) {
        float2 fa = __bfloat1622float2(pa[k]);
        float2 fb = __bfloat1622float2(pb[k]);
        s += fa.x * fb.x + fa.y * fb.y;
    }
    return s;
}

__global__ void pos_kernel(const float* __restrict__ homo) {
    int warp = threadIdx.x >> 5;
    int lane = threadIdx.x & 31;
    int item = blockIdx.x * 8 + warp;   // 0 .. 14399
    float contrib = 0.f;

    if (item < NB * M) {
        int n  = item / M;
        int ij = item % M;
        int i  = ij / WR, j = ij % WR;
        float x = j * 8 + 4.f, y = i * 8 + 4.f;
        const float* Hm = homo + n * 9;
        float wxh = Hm[0] * x + Hm[1] * y + Hm[2];
        float wyh = Hm[3] * x + Hm[4] * y + Hm[5];
        float wzh = Hm[6] * x + Hm[7] * y + Hm[8];
        float wx = wxh / wzh, wy = wyh / wzh;
        float vmv = d_vm[n * MP + ij];

        const uint4 bvec = ((const uint4*)(d_D2t + ((size_t)n * MP + ij) * C))[lane];

        int hs = (int)floorf((wy - 11.5f) * 0.125f);
        int ws = (int)floorf((wx - 11.5f) * 0.125f);
        for (int hh = hs; hh < hs + 4; hh++) {
            if (hh < 0 || hh >= HR) continue;
            float dy = hh * 8 + 4.f - wy;
            for (int wc = ws; wc < ws + 4; wc++) {
                if (wc < 0 || wc >= WR) continue;
                float dx = wc * 8 + 4.f - wx;
                if (dx * dx + dy * dy <= 56.25f) {   // dist <= 7.5
                    const uint4 avec =
                        ((const uint4*)(d_D1t + ((size_t)n * MP + hh * WR + wc) * C))[lane];
                    float dt = dot8(avec, bvec);
                    #pragma unroll
                    for (int o = 16; o > 0; o >>= 1)
                        dt += __shfl_down_sync(0xffffffffu, dt, o);
                    dt = __shfl_sync(0xffffffffu, dt, 0);
                    if (lane == 0)
                        contrib += vmv * (fmaxf(1.f - dt, 0.f) - fmaxf(dt - 0.2f, 0.f));
                }
            }
        }
    }

    __shared__ float wsh[8];
    if (lane == 0) wsh[warp] = contrib;
    __syncthreads();
    if (threadIdx.x == 0) {
        float t = 0.f;
        #pragma unroll
        for (int w = 0; w < 8; w++) t += wsh[w];
        d_partB[blockIdx.x] = t;
    }
}

// ---------------------------------------------------------------------------
// Final deterministic reduction (232 strip partials on TC path).
// ---------------------------------------------------------------------------
__global__ void final_kernel(float* __restrict__ out) {
    __shared__ float sh[256];
    int tid = threadIdx.x;

    float s = 0.f;
    for (int k = tid; k < NB * GB * 2; k += 256) s += d_partA[k];
    for (int k = tid; k < NPOSB; k += 256) s += d_partB[k];
    float v = 0.f;
    for (int k = tid; k < NB * MP; k += 256) v += d_vm[k];  // pads are 0

    sh[tid] = s;
    __syncthreads();
    for (int o = 128; o > 0; o >>= 1) {
        if (tid < o) sh[tid] += sh[tid + o];
        __syncthreads();
    }
    float total = sh[0];
    __syncthreads();

    sh[tid] = v;
    __syncthreads();
    for (int o = 128; o > 0; o >>= 1) {
        if (tid < o) sh[tid] += sh[tid + o];
        __syncthreads();
    }
    if (tid == 0)
        out[0] = total / (3600.f * sh[0]);   // LOSS_LAMBDA = 1
}

// ---------------------------------------------------------------------------
// Host: tensormap construction via driver entry point (no -lcuda needed).
// ---------------------------------------------------------------------------
typedef CUresult (*PFN_encodeTiled)(
    CUtensorMap*, CUtensorMapDataType, cuuint32_t, void*,
    const cuuint64_t*, const cuuint64_t*, const cuuint32_t*, const cuuint32_t*,
    CUtensorMapInterleave, CUtensorMapSwizzle, CUtensorMapL2promotion,
    CUtensorMapFloatOOBfill);

static void build_tmap(PFN_encodeTiled enc, CUtensorMap* tm, void* gptr) {
    cuuint64_t dims[3]    = {C, MP, NB};
    cuuint64_t strides[2] = {(cuuint64_t)C * 2, (cuuint64_t)MP * C * 2};
    cuuint32_t box[3]     = {64, 128, 1};
    cuuint32_t es[3]      = {1, 1, 1};
    enc(tm, CU_TENSOR_MAP_DATA_TYPE_BFLOAT16, 3, gptr, dims, strides, box, es,
        CU_TENSOR_MAP_INTERLEAVE_NONE, CU_TENSOR_MAP_SWIZZLE_128B,
        CU_TENSOR_MAP_L2_PROMOTION_L2_128B, CU_TENSOR_MAP_FLOAT_OOB_FILL_NONE);
}

extern "C" void kernel_launch(void* const* d_in, const int* in_sizes, int n_in,
                              void* d_out, int out_size) {
    const float* desc1 = nullptr;
    const float* desc2 = nullptr;
    const float* homo  = nullptr;
    const float* vis   = nullptr;
    for (int k = 0; k < n_in; k++) {
        if (in_sizes[k] == NB * C * M) {
            if (!desc1) desc1 = (const float*)d_in[k];
            else if (!desc2) desc2 = (const float*)d_in[k];
        } else if (in_sizes[k] == NB * 9) {
            homo = (const float*)d_in[k];
        } else if (in_sizes[k] == NB * HH * WW) {
            vis = (const float*)d_in[k];
        }
    }

    // tensormaps for the GEMM TMA loads (host-side only; baked into the graph)
    CUtensorMap tA, tB;
    {
        void* fn = nullptr;
        cudaDriverEntryPointQueryResult qr;
#if CUDART_VERSION >= 12050
        cudaGetDriverEntryPointByVersion("cuTensorMapEncodeTiled", &fn, 12000,
                                         cudaEnableDefault, &qr);
#else
        cudaGetDriverEntryPoint("cuTensorMapEncodeTiled", &fn,
                                cudaEnableDefault, &qr);
#endif
        void* pA = nullptr; void* pB = nullptr;
        cudaGetSymbolAddress(&pA, d_D1t);
        cudaGetSymbolAddress(&pB, d_D2t);
        if (fn) {
            build_tmap((PFN_encodeTiled)fn, &tA, pA);
            build_tmap((PFN_encodeTiled)fn, &tB, pB);
        }
    }

    // Idempotent, capture-safe. 96KB dynamic + align slack.
    cudaFuncSetAttribute(gemm_tc_kernel,
                         cudaFuncAttributeMaxDynamicSharedMemorySize, 99328);

    transpose_kernel<<<dim3(116, 8, NB), dim3(32, 8)>>>(desc1, desc2);
    vm_kernel<<<(NB * MP + 255) / 256, 256>>>(vis);
    gemm_tc_kernel<<<dim3(GB, 2, NB), 288, 99328>>>(tA, tB);    // active on "a"
    gemm_simt_kernel<<<dim3(GB, 2, NB), 256>>>();               // active otherwise
    pos_kernel<<<NPOSB, 256>>>(homo);
    final_kernel<<<1, 256>>>((float*)d_out);
}

// round 13
// speedup vs baseline: 1.1643x; 1.1106x over previous
#include <cuda_runtime.h>
#include <cuda.h>
#include <cuda_bf16.h>
#include <cstdint>

// ---------------------------------------------------------------------------
// Arch feature gate: tcgen05/TMEM are "a"-target-only. Non-"a" passes compile
// the SIMT fallback instead; host picks the matching kernel by device CC.
// ---------------------------------------------------------------------------
#if defined(__CUDA_ARCH__) && (defined(__CUDA_ARCH_FEAT_SM103_ALL) || defined(__CUDA_ARCH_FEAT_SM100_ALL))
#define HAS_TC 1
#else
#define HAS_TC 0
#endif

// Problem constants
#define NB 4
#define C  256
#define HR 60
#define WR 60
#define M  3600          // HR*WR
#define MP 3712          // padded to 29*128
#define GS 8
#define HH 480
#define WW 480

#define BM 128
#define BN 128
#define BK 8
#define GB 29            // tiles per GEMM dim
#define NT 29            // A tiles per strip
#define NH (2 * NT)      // K=128 half-tiles
#define NPOSB 1800

// idesc kind::f16: dtype=F32(1<<4), atype=BF16(1<<7), btype=BF16(1<<10),
// N/8 << 17, M/16 << 24  ->  M=128, N=128
#define MMA_IDESC 0x8200490u

// smem layout (dynamic, 1024-aligned): A half-tile slots 0..3 @ s*32768
// (32KB each), B @ 131072 (64KB). Total 192KB -> occupancy 1.
#define A_SLOT(s)  ((uint32_t)(s) * 32768u)
#define B_OFF      131072u

// __device__ scratch (no allocation allowed)
__device__ __align__(16) __nv_bfloat16 d_D1t[(size_t)NB * MP * C];  // [n][m][c] bf16
__device__ __align__(16) __nv_bfloat16 d_D2t[(size_t)NB * MP * C];
__device__ float d_D1p[NB * C * MP];                                // fp32 fallback
__device__ float d_D2p[NB * C * MP];
__device__ float d_vm[NB * MP];
__device__ float d_partA[NB * GB];
__device__ float d_partB[NPOSB];

// ---------------------------------------------------------------------------
// Helpers
// ---------------------------------------------------------------------------
__device__ __forceinline__ uint32_t smem_u32(const void* p) {
    uint32_t a;
    asm("{ .reg .u64 t; cvta.to.shared.u64 t, %1; cvt.u32.u64 %0, t; }" : "=r"(a) : "l"(p));
    return a;
}

#if HAS_TC
__device__ __forceinline__ uint32_t elect_one() {
    uint32_t p;
    asm volatile("{ .reg .pred p; elect.sync _|p, 0xFFFFFFFF; selp.b32 %0, 1, 0, p; }" : "=r"(p));
    return p;
}
static __device__ __forceinline__ uint64_t make_desc(uint32_t addr) {
    // SW128, version=1(Blackwell), SBO=64, LBO=1
    const uint64_t base = (uint64_t(2) << 61) | (uint64_t(1) << 46)
                        | (uint64_t(64) << 32) | (uint64_t(1) << 16);
    return base | ((uint64_t)(addr >> 4) & 0x3FFF);
}
__device__ __forceinline__ void mma_f16_ss_cg1(uint32_t d_tmem, uint64_t a_desc,
                                               uint64_t b_desc, uint32_t idesc,
                                               uint32_t enable) {
    asm volatile(
        "{\n\t.reg .pred p;\n\t"
        "setp.ne.u32 p, %4, 0;\n\t"
        "tcgen05.mma.cta_group::1.kind::f16 [%0], %1, %2, %3, {%5, %5, %5, %5}, p;\n\t}"
        :: "r"(d_tmem), "l"(a_desc), "l"(b_desc), "r"(idesc), "r"(enable), "r"(0u)
        : "memory");
}
__device__ __forceinline__ void mbar_wait(uint32_t mbar, uint32_t parity) {
    uint32_t done;
    asm volatile(
        "{\n\t.reg .pred p;\n\t"
        "mbarrier.try_wait.parity.acquire.cta.shared::cta.b64 p, [%1], %2;\n\t"
        "selp.b32 %0, 1, 0, p;\n\t}"
        : "=r"(done) : "r"(mbar), "r"(parity) : "memory");
    if (!done) {
        asm volatile(
            "{\n\t.reg .pred P1;\n\t"
            "WL_%=:\n\t"
            "mbarrier.try_wait.parity.acquire.cta.shared::cta.b64 P1, [%0], %1, 0x989680;\n\t"
            "@P1 bra.uni WD_%=;\n\t"
            "bra.uni WL_%=;\n\t"
            "WD_%=:\n\t}"
            :: "r"(mbar), "r"(parity) : "memory");
    }
}
__device__ __forceinline__ void mbar_arrive(uint32_t mbar) {
    asm volatile("mbarrier.arrive.release.cta.shared::cta.b64 _, [%0];"
                 :: "r"(mbar) : "memory");
}
__device__ __forceinline__ void mbar_expect_tx(uint32_t mbar, uint32_t bytes) {
    asm volatile("mbarrier.arrive.expect_tx.shared.b64 _, [%0], %1;"
                 :: "r"(mbar), "r"(bytes) : "memory");
}
__device__ __forceinline__ void tma3d(uint32_t dst, const CUtensorMap* tmap,
                                      int x, int y, int z, uint32_t mbar) {
    asm volatile(
        "cp.async.bulk.tensor.3d.shared::cta.global.tile.mbarrier::complete_tx::bytes "
        "[%0], [%1, {%2, %3, %4}], [%5];"
        :: "r"(dst), "l"((uint64_t)tmap), "r"(x), "r"(y), "r"(z), "r"(mbar)
        : "memory");
}

#define LDTM_X32(dr, addr)                                                     \
    asm volatile(                                                              \
        "tcgen05.ld.sync.aligned.32x32b.x32.b32 "                              \
        "{%0, %1, %2, %3, %4, %5, %6, %7, "                                    \
        " %8, %9, %10, %11, %12, %13, %14, %15, "                              \
        " %16, %17, %18, %19, %20, %21, %22, %23, "                            \
        " %24, %25, %26, %27, %28, %29, %30, %31}, [%32];"                     \
        : "=r"((dr)[0]),  "=r"((dr)[1]),  "=r"((dr)[2]),  "=r"((dr)[3]),       \
          "=r"((dr)[4]),  "=r"((dr)[5]),  "=r"((dr)[6]),  "=r"((dr)[7]),       \
          "=r"((dr)[8]),  "=r"((dr)[9]),  "=r"((dr)[10]), "=r"((dr)[11]),      \
          "=r"((dr)[12]), "=r"((dr)[13]), "=r"((dr)[14]), "=r"((dr)[15]),      \
          "=r"((dr)[16]), "=r"((dr)[17]), "=r"((dr)[18]), "=r"((dr)[19]),      \
          "=r"((dr)[20]), "=r"((dr)[21]), "=r"((dr)[22]), "=r"((dr)[23]),      \
          "=r"((dr)[24]), "=r"((dr)[25]), "=r"((dr)[26]), "=r"((dr)[27]),      \
          "=r"((dr)[28]), "=r"((dr)[29]), "=r"((dr)[30]), "=r"((dr)[31])       \
        : "r"(addr))

// Epilogue: this warp reads 64 columns [c0, c0+64) of its 32-lane
// subpartition. Hinge via max(d, 0.2); constant part folded out at the end.
__device__ __forceinline__ void epi64(uint32_t tsrc, const float* vmv, float& local) {
    uint32_t dr[64];
    LDTM_X32(dr,      tsrc);
    LDTM_X32(dr + 32, tsrc + 32);
    asm volatile("tcgen05.wait::ld.sync.aligned;" ::: "memory");
    float a0 = 0.f, a1 = 0.f, a2 = 0.f, a3 = 0.f;
    #pragma unroll
    for (int k = 0; k < 64; k += 4) {
        a0 = fmaf(vmv[k + 0], fmaxf(__uint_as_float(dr[k + 0]), 0.2f), a0);
        a1 = fmaf(vmv[k + 1], fmaxf(__uint_as_float(dr[k + 1]), 0.2f), a1);
        a2 = fmaf(vmv[k + 2], fmaxf(__uint_as_float(dr[k + 2]), 0.2f), a2);
        a3 = fmaf(vmv[k + 3], fmaxf(__uint_as_float(dr[k + 3]), 0.2f), a3);
    }
    local += (a0 + a1) + (a2 + a3);
}
#endif

// ---------------------------------------------------------------------------
// Transpose + pad + bf16 convert: [n][c][m] f32 -> [n][m][c] bf16.
// 64-wide c-tiles so the bf16 write phase issues full 128B/warp transactions
// (bfloat162 stores). Non-"a" targets also write padded fp32 copies.
// ---------------------------------------------------------------------------
__global__ void transpose_kernel(const float* __restrict__ d1,
                                 const float* __restrict__ d2) {
    __shared__ float t1[64][33];
    __shared__ float t2[64][33];
    int m0 = blockIdx.x * 32, c0 = blockIdx.y * 64, n = blockIdx.z;
    int tx = threadIdx.x, ty = threadIdx.y;   // 32 x 8

    #pragma unroll
    for (int i = 0; i < 8; i++) {
        int c = c0 + ty + i * 8, m = m0 + tx;
        float v1 = 0.f, v2 = 0.f;
        if (m < M) {
            size_t idx = ((size_t)n * C + c) * M + m;
            v1 = d1[idx]; v2 = d2[idx];
        }
        t1[ty + i * 8][tx] = v1;
        t2[ty + i * 8][tx] = v2;
#if !HAS_TC
        size_t o = ((size_t)n * C + c) * MP + m;
        d_D1p[o] = v1;
        d_D2p[o] = v2;
#endif
    }
    __syncthreads();
    #pragma unroll
    for (int i = 0; i < 4; i++) {
        int m = m0 + ty + i * 8;          // always < MP (m0 <= 3680)
        int c = c0 + tx * 2;
        size_t o = ((size_t)n * MP + m) * C + c;
        __nv_bfloat162 b1, b2;
        b1.x = __float2bfloat16(t1[tx * 2][ty + i * 8]);
        b1.y = __float2bfloat16(t1[tx * 2 + 1][ty + i * 8]);
        b2.x = __float2bfloat16(t2[tx * 2][ty + i * 8]);
        b2.y = __float2bfloat16(t2[tx * 2 + 1][ty + i * 8]);
        *(__nv_bfloat162*)(d_D1t + o) = b1;
        *(__nv_bfloat162*)(d_D2t + o) = b2;
    }
}

// ---------------------------------------------------------------------------
// vm[n, i, j] = prod of 8x8 block of vis_mask1; padded entries are 0.
// ---------------------------------------------------------------------------
__global__ void vm_kernel(const float* __restrict__ vis) {
    int idx = blockIdx.x * blockDim.x + threadIdx.x;
    if (idx >= NB * MP) return;
    int mp = idx % MP;
    int n  = idx / MP;
    float p = 0.f;
    if (mp < M) {
        int i = mp / WR, j = mp % WR;
        p = 1.f;
        const float* base = vis + n * HH * WW + (i * GS) * WW + j * GS;
        #pragma unroll
        for (int a = 0; a < GS; a++)
            #pragma unroll
            for (int b = 0; b < GS; b++)
                p *= base[a * WW + b];
    }
    d_vm[idx] = p;
}

// ---------------------------------------------------------------------------
// 3-role warp-specialized persistent-strip tcgen05 GEMM.
// Grid (29, 1, 4), 320 threads:
//   warps 0-7: pure epilogue (LDTM + hinge + reduce)
//   warp  8  : pure MMA (wait load -> 8 MMAs/half -> commit)
//   warp  9  : pure TMA producer (wait slot exec done -> TMA next half)
// B strip (full K, 64KB) TMA'd once; A streamed as K=128 half-tiles through
// a 4-slot ring (32KB). Slot s receives halves h === s (mod 4): odd slots
// carry only odd halves, so tile completion = the odd-half commit on slot
// 1/3 with clean parity (R8 mapping).
// mbarriers: load[4] (cnt1+tx32KB), half[4] (cnt1, commit), epi[2] (cnt256),
//            B (cnt1+tx64KB).
// ---------------------------------------------------------------------------
__global__ __launch_bounds__(320, 1) void gemm_tc_kernel(
    const __grid_constant__ CUtensorMap tmapA,
    const __grid_constant__ CUtensorMap tmapB) {
#if HAS_TC
    extern __shared__ char dyn_sm[];
    __shared__ uint32_t s_tmem[1];
    __shared__ __align__(8) unsigned long long s_mbar[11]; // load[4] half[4] epi[2] B
    __shared__ float s_red[8];

    const int n   = blockIdx.z;
    const int xs  = blockIdx.x;
    const int tid = threadIdx.x;
    const int wid = tid >> 5, lid = tid & 31;

    uint32_t raw  = smem_u32(dyn_sm);
    uint32_t base = (raw + 1023u) & ~1023u;

    if (wid == 8) {
        asm volatile("tcgen05.alloc.cta_group::1.sync.aligned.shared::cta.b32 [%0], %1;"
                     :: "r"(smem_u32(s_tmem)), "r"(256u) : "memory");
        asm volatile("tcgen05.relinquish_alloc_permit.cta_group::1.sync.aligned;");
    }
    if (tid == 0) {
        #pragma unroll
        for (int k = 0; k < 8; k++)   // load[4], half[4]: count 1
            asm volatile("mbarrier.init.shared.b64 [%0], %1;"
                         :: "r"(smem_u32(&s_mbar[k])), "r"(1u) : "memory");
        #pragma unroll
        for (int k = 8; k < 10; k++)  // epi[2]: count 256
            asm volatile("mbarrier.init.shared.b64 [%0], %1;"
                         :: "r"(smem_u32(&s_mbar[k])), "r"(256u) : "memory");
        asm volatile("mbarrier.init.shared.b64 [%0], %1;"
                     :: "r"(smem_u32(&s_mbar[10])), "r"(1u) : "memory");   // B
    }
    __syncthreads();
    const uint32_t tmem = s_tmem[0];
    uint32_t mb_load[4], mb_half[4], mb_epi[2], mb_B;
    #pragma unroll
    for (int k = 0; k < 4; k++) { mb_load[k] = smem_u32(&s_mbar[k]); mb_half[k] = smem_u32(&s_mbar[4 + k]); }
    mb_epi[0] = smem_u32(&s_mbar[8]); mb_epi[1] = smem_u32(&s_mbar[9]);
    mb_B = smem_u32(&s_mbar[10]);

    if (wid < 8) {
        // ---------------- pure epilogue warps (256 threads) ----------------
        const int c0 = (wid >= 4) ? 64 : 0;
        float vmv[64];
        float sum_vm = 0.f;
        {
            const float* vmb = d_vm + n * MP + xs * BN + c0;
            #pragma unroll
            for (int k = 0; k < 64; k++) { vmv[k] = vmb[k]; sum_vm += vmb[k]; }
        }

        float local = 0.f;
        #pragma unroll 1
        for (int tt = 0; tt < NT; tt++) {
            const int s = (tt & 1) ? 3 : 1;           // slot of odd half 2tt+1
            mbar_wait(mb_half[s], (uint32_t)((tt >> 1) & 1));
            asm volatile("tcgen05.fence::after_thread_sync;" ::: "memory");
            epi64(tmem + (tt & 1) * 128 + c0, vmv, local);
            mbar_arrive(mb_epi[tt & 1]);              // tmem[tt&1] consumed
        }

        local -= 0.2f * (float)NT * sum_vm;           // fold out hinge constant

        #pragma unroll
        for (int o = 16; o > 0; o >>= 1)
            local += __shfl_down_sync(0xffffffffu, local, o);
        if (lid == 0) s_red[wid] = local;
    } else if (wid == 8) {
        // ---------------- pure MMA warp ----------------
        const bool leader = elect_one() != 0;
        int pl[4] = {0, 0, 0, 0};
        int pe[2] = {0, 0};

        mbar_wait(mb_B, 0u);                          // B resident

        #pragma unroll 1
        for (int h = 0; h < NH; h++) {
            const int s = h & 3, t = h >> 1;
            mbar_wait(mb_load[s], (uint32_t)(pl[s] & 1));
            pl[s]++;
            if (!(h & 1) && t >= 2) {                 // tmem[t&1] free of t-2 reads
                mbar_wait(mb_epi[t & 1], (uint32_t)(pe[t & 1] & 1));
                pe[t & 1]++;
            }
            if (leader) {
                const uint32_t dt = tmem + (t & 1) * 128;
                #pragma unroll
                for (int cc = 0; cc < 2; cc++) {
                    uint64_t ad = make_desc(base + A_SLOT(s) + cc * 16384u);
                    uint64_t bd = make_desc(base + B_OFF + ((h & 1) * 2 + cc) * 16384u);
                    #pragma unroll
                    for (int ks = 0; ks < 4; ks++)
                        mma_f16_ss_cg1(dt, ad + ks * 2, bd + ks * 2, MMA_IDESC,
                                       (uint32_t)((h & 1) | cc | ks));
                }
                asm volatile(
                    "tcgen05.commit.cta_group::1.mbarrier::arrive::one.shared::cluster.b64 [%0];"
                    :: "r"(mb_half[s]) : "memory");
            }
        }
    } else {
        // ---------------- pure TMA producer warp ----------------
        const bool leader = elect_one() != 0;

        // TMA half h (2 chunks of 64 cols = 32KB) into slot h&3
        auto tma_half = [&](int h) {
            const int s = h & 3, t = h >> 1, ko = (h & 1) * 128;
            mbar_expect_tx(mb_load[s], 32768u);
            tma3d(base + A_SLOT(s),          &tmapA, ko,      t * 128, n, mb_load[s]);
            tma3d(base + A_SLOT(s) + 16384u, &tmapA, ko + 64, t * 128, n, mb_load[s]);
        };

        if (leader) {
            mbar_expect_tx(mb_B, 65536u);
            #pragma unroll
            for (int cc = 0; cc < 4; cc++)
                tma3d(base + B_OFF + cc * 16384u, &tmapB, cc * 64, xs * 128, n, mb_B);
            tma_half(0);
            tma_half(1);
            tma_half(2);
            tma_half(3);
        }

        int ph[4] = {0, 0, 0, 0};
        #pragma unroll 1
        for (int h = 4; h < NH; h++) {
            const int s = h & 3;
            mbar_wait(mb_half[s], (uint32_t)(ph[s] & 1));   // exec of h-4 done
            ph[s]++;
            if (leader) tma_half(h);
        }
    }

    __syncthreads();
    if (tid == 0) {
        float t = 0.f;
        #pragma unroll
        for (int w = 0; w < 8; w++) t += s_red[w];
        d_partA[n * GB + xs] = t;
    }
    if (wid == 8) {
        asm volatile("tcgen05.dealloc.cta_group::1.sync.aligned.b32 %0, %1;"
                     :: "r"(tmem), "r"(256u));
    }
#endif
}

// ---------------------------------------------------------------------------
// Fallback SIMT fp32 GEMM, persistent strips (launched only when the device
// lacks tcgen05). Grid (29, 1, 4).
// ---------------------------------------------------------------------------
__global__ __launch_bounds__(256, 1) void gemm_simt_kernel() {
#if !HAS_TC
    int n = blockIdx.z, xs = blockIdx.x;
    const float* Bb = d_D2p + n * C * MP + xs * BN;

    __shared__ float As[2][BK][BM];
    __shared__ float Bs[2][BK][BN];

    int tid  = threadIdx.x;
    int tx   = tid & 15;
    int ty2  = tid >> 4;
    int lrow = tid >> 5;
    int lcol = (tid & 31) << 2;

    float vmv[8];
    #pragma unroll
    for (int j = 0; j < 8; j++)
        vmv[j] = d_vm[n * MP + xs * BN + tx * 8 + j];

    float total = 0.f;

    #pragma unroll 1
    for (int ty = 0; ty < GB; ty++) {
        const float* Ab = d_D1p + n * C * MP + ty * BM;

        float acc[8][8];
        #pragma unroll
        for (int i = 0; i < 8; i++)
            #pragma unroll
            for (int j = 0; j < 8; j++) acc[i][j] = 0.f;

        *(float4*)&As[0][lrow][lcol] = *(const float4*)&Ab[lrow * MP + lcol];
        *(float4*)&Bs[0][lrow][lcol] = *(const float4*)&Bb[lrow * MP + lcol];
        __syncthreads();

        #pragma unroll 1
        for (int k0 = 0; k0 < C; k0 += BK) {
            int buf = (k0 >> 3) & 1;
            if (k0 + BK < C) {
                *(float4*)&As[buf ^ 1][lrow][lcol] =
                    *(const float4*)&Ab[(k0 + BK + lrow) * MP + lcol];
                *(float4*)&Bs[buf ^ 1][lrow][lcol] =
                    *(const float4*)&Bb[(k0 + BK + lrow) * MP + lcol];
            }
            #pragma unroll
            for (int kk = 0; kk < BK; kk++) {
                float a[8], b[8];
                *(float4*)&a[0] = *(const float4*)&As[buf][kk][ty2 * 8];
                *(float4*)&a[4] = *(const float4*)&As[buf][kk][ty2 * 8 + 4];
                *(float4*)&b[0] = *(const float4*)&Bs[buf][kk][tx * 8];
                *(float4*)&b[4] = *(const float4*)&Bs[buf][kk][tx * 8 + 4];
                #pragma unroll
                for (int i = 0; i < 8; i++)
                    #pragma unroll
                    for (int j = 0; j < 8; j++)
                        acc[i][j] = fmaf(a[i], b[j], acc[i][j]);
            }
            __syncthreads();
        }

        #pragma unroll
        for (int i = 0; i < 8; i++)
            #pragma unroll
            for (int j = 0; j < 8; j++)
                total += vmv[j] * fmaxf(acc[i][j] - 0.2f, 0.f);
    }

    #pragma unroll
    for (int o = 16; o > 0; o >>= 1)
        total += __shfl_down_sync(0xffffffffu, total, o);

    __shared__ float wsum[8];
    if ((tid & 31) == 0) wsum[tid >> 5] = total;
    __syncthreads();
    if (tid == 0) {
        float t = 0.f;
        #pragma unroll
        for (int w = 0; w < 8; w++) t += wsum[w];
        d_partA[n * GB + xs] = t;
    }
#endif
}

// ---------------------------------------------------------------------------
// Positive-pair correction (coalesced bf16 dots on transposed arrays).
// ---------------------------------------------------------------------------
__device__ __forceinline__ float dot8(uint4 a, uint4 b) {
    const __nv_bfloat162* pa = (const __nv_bfloat162*)&a;
    const __nv_bfloat162* pb = (const __nv_bfloat162*)&b;
    float s = 0.f;
    #pragma unroll
    for (int k = 0; k < 4; k++) {
        float2 fa = __bfloat1622float2(pa[k]);
        float2 fb = __bfloat1622float2(pb[k]);
        s += fa.x * fb.x + fa.y * fb.y;
    }
    return s;
}

__global__ void pos_kernel(const float* __restrict__ homo) {
    int warp = threadIdx.x >> 5;
    int lane = threadIdx.x & 31;
    int item = blockIdx.x * 8 + warp;   // 0 .. 14399
    float contrib = 0.f;

    if (item < NB * M) {
        int n  = item / M;
        int ij = item % M;
        int i  = ij / WR, j = ij % WR;
        float x = j * 8 + 4.f, y = i * 8 + 4.f;
        const float* Hm = homo + n * 9;
        float wxh = Hm[0] * x + Hm[1] * y + Hm[2];
        float wyh = Hm[3] * x + Hm[4] * y + Hm[5];
        float wzh = Hm[6] * x + Hm[7] * y + Hm[8];
        float wx = wxh / wzh, wy = wyh / wzh;
        float vmv = d_vm[n * MP + ij];

        const uint4 bvec = ((const uint4*)(d_D2t + ((size_t)n * MP + ij) * C))[lane];

        int hs = (int)floorf((wy - 11.5f) * 0.125f);
        int ws = (int)floorf((wx - 11.5f) * 0.125f);
        for (int hh = hs; hh < hs + 4; hh++) {
            if (hh < 0 || hh >= HR) continue;
            float dy = hh * 8 + 4.f - wy;
            for (int wc = ws; wc < ws + 4; wc++) {
                if (wc < 0 || wc >= WR) continue;
                float dx = wc * 8 + 4.f - wx;
                if (dx * dx + dy * dy <= 56.25f) {   // dist <= 7.5
                    const uint4 avec =
                        ((const uint4*)(d_D1t + ((size_t)n * MP + hh * WR + wc) * C))[lane];
                    float dt = dot8(avec, bvec);
                    #pragma unroll
                    for (int o = 16; o > 0; o >>= 1)
                        dt += __shfl_down_sync(0xffffffffu, dt, o);
                    dt = __shfl_sync(0xffffffffu, dt, 0);
                    if (lane == 0)
                        contrib += vmv * (fmaxf(1.f - dt, 0.f) - fmaxf(dt - 0.2f, 0.f));
                }
            }
        }
    }

    __shared__ float wsh[8];
    if (lane == 0) wsh[warp] = contrib;
    __syncthreads();
    if (threadIdx.x == 0) {
        float t = 0.f;
        #pragma unroll
        for (int w = 0; w < 8; w++) t += wsh[w];
        d_partB[blockIdx.x] = t;
    }
}

// ---------------------------------------------------------------------------
// Final deterministic reduction (116 strip partials on both paths).
// ---------------------------------------------------------------------------
__global__ void final_kernel(float* __restrict__ out) {
    __shared__ float sh[256];
    int tid = threadIdx.x;

    float s = 0.f;
    for (int k = tid; k < NB * GB; k += 256) s += d_partA[k];
    for (int k = tid; k < NPOSB; k += 256) s += d_partB[k];
    float v = 0.f;
    for (int k = tid; k < NB * MP; k += 256) v += d_vm[k];  // pads are 0

    sh[tid] = s;
    __syncthreads();
    for (int o = 128; o > 0; o >>= 1) {
        if (tid < o) sh[tid] += sh[tid + o];
        __syncthreads();
    }
    float total = sh[0];
    __syncthreads();

    sh[tid] = v;
    __syncthreads();
    for (int o = 128; o > 0; o >>= 1) {
        if (tid < o) sh[tid] += sh[tid + o];
        __syncthreads();
    }
    if (tid == 0)
        out[0] = total / (3600.f * sh[0]);   // LOSS_LAMBDA = 1
}

// ---------------------------------------------------------------------------
// Host: tensormap construction via driver entry point (no -lcuda needed).
// ---------------------------------------------------------------------------
typedef CUresult (*PFN_encodeTiled)(
    CUtensorMap*, CUtensorMapDataType, cuuint32_t, void*,
    const cuuint64_t*, const cuuint64_t*, const cuuint32_t*, const cuuint32_t*,
    CUtensorMapInterleave, CUtensorMapSwizzle, CUtensorMapL2promotion,
    CUtensorMapFloatOOBfill);

static void build_tmap(PFN_encodeTiled enc, CUtensorMap* tm, void* gptr) {
    cuuint64_t dims[3]    = {C, MP, NB};
    cuuint64_t strides[2] = {(cuuint64_t)C * 2, (cuuint64_t)MP * C * 2};
    cuuint32_t box[3]     = {64, 128, 1};
    cuuint32_t es[3]      = {1, 1, 1};
    enc(tm, CU_TENSOR_MAP_DATA_TYPE_BFLOAT16, 3, gptr, dims, strides, box, es,
        CU_TENSOR_MAP_INTERLEAVE_NONE, CU_TENSOR_MAP_SWIZZLE_128B,
        CU_TENSOR_MAP_L2_PROMOTION_L2_128B, CU_TENSOR_MAP_FLOAT_OOB_FILL_NONE);
}

extern "C" void kernel_launch(void* const* d_in, const int* in_sizes, int n_in,
                              void* d_out, int out_size) {
    const float* desc1 = nullptr;
    const float* desc2 = nullptr;
    const float* homo  = nullptr;
    const float* vis   = nullptr;
    for (int k = 0; k < n_in; k++) {
        if (in_sizes[k] == NB * C * M) {
            if (!desc1) desc1 = (const float*)d_in[k];
            else if (!desc2) desc2 = (const float*)d_in[k];
        } else if (in_sizes[k] == NB * 9) {
            homo = (const float*)d_in[k];
        } else if (in_sizes[k] == NB * HH * WW) {
            vis = (const float*)d_in[k];
        }
    }

    // Device gate: sm_10x has tcgen05; pick ONE gemm path (saves a dead launch).
    int dev = 0, cc_major = 0;
    cudaGetDevice(&dev);
    cudaDeviceGetAttribute(&cc_major, cudaDevAttrComputeCapabilityMajor, dev);
    const bool use_tc = (cc_major >= 10);

    // tensormaps for the GEMM TMA loads (host-side only; baked into the graph)
    CUtensorMap tA, tB;
    if (use_tc) {
        void* fn = nullptr;
        cudaDriverEntryPointQueryResult qr;
#if CUDART_VERSION >= 12050
        cudaGetDriverEntryPointByVersion("cuTensorMapEncodeTiled", &fn, 12000,
                                         cudaEnableDefault, &qr);
#else
        cudaGetDriverEntryPoint("cuTensorMapEncodeTiled", &fn,
                                cudaEnableDefault, &qr);
#endif
        void* pA = nullptr; void* pB = nullptr;
        cudaGetSymbolAddress(&pA, d_D1t);
        cudaGetSymbolAddress(&pB, d_D2t);
        if (fn) {
            build_tmap((PFN_encodeTiled)fn, &tA, pA);
            build_tmap((PFN_encodeTiled)fn, &tB, pB);
        }
        // Idempotent, capture-safe. 192KB dynamic + align slack.
        cudaFuncSetAttribute(gemm_tc_kernel,
                             cudaFuncAttributeMaxDynamicSharedMemorySize, 197632);
    }

    transpose_kernel<<<dim3(116, 4, NB), dim3(32, 8)>>>(desc1, desc2);
    vm_kernel<<<(NB * MP + 255) / 256, 256>>>(vis);
    if (use_tc)
        gemm_tc_kernel<<<dim3(GB, 1, NB), 320, 197632>>>(tA, tB);
    else
        gemm_simt_kernel<<<dim3(GB, 1, NB), 256>>>();
    pos_kernel<<<NPOSB, 256>>>(homo);
    final_kernel<<<1, 256>>>((float*)d_out);
}

// round 16
// speedup vs baseline: 1.2537x; 1.0768x over previous
#include <cuda_runtime.h>
#include <cuda.h>
#include <cuda_bf16.h>
#include <cstdint>

// ---------------------------------------------------------------------------
// Arch feature gate: tcgen05/TMEM are "a"-target-only. Non-"a" passes compile
// the SIMT fallback instead; host picks the matching kernel by device CC.
// ---------------------------------------------------------------------------
#if defined(__CUDA_ARCH__) && (defined(__CUDA_ARCH_FEAT_SM103_ALL) || defined(__CUDA_ARCH_FEAT_SM100_ALL))
#define HAS_TC 1
#else
#define HAS_TC 0
#endif

// Problem constants
#define NB 4
#define C  256
#define HR 60
#define WR 60
#define M  3600          // HR*WR
#define MP 3712          // padded to 29*128
#define GS 8
#define HH 480
#define WW 480

#define BM 128
#define BN 128
#define BK 8
#define GB 29            // tiles per GEMM dim
#define NT 29            // A tiles per strip
#define NH (2 * NT)      // K=128 half-tiles
#define NPOSB 450        // pos blocks: 32 items each (8 warps x 4 items)

// idesc kind::f16: dtype=F32(1<<4), atype=BF16(1<<7), btype=BF16(1<<10),
// N/8 << 17, M/16 << 24  ->  M=128, N=128
#define MMA_IDESC 0x8200490u

// smem layout (dynamic, 1024-aligned): A half-tile slots 0..3 @ s*32768
// (32KB each), B @ 131072 (64KB). Total 192KB -> occupancy 1.
#define A_SLOT(s)  ((uint32_t)(s) * 32768u)
#define B_OFF      131072u

// __device__ scratch (no allocation allowed)
__device__ __align__(16) __nv_bfloat16 d_D1t[(size_t)NB * MP * C];  // [n][m][c] bf16
__device__ __align__(16) __nv_bfloat16 d_D2t[(size_t)NB * MP * C];
__device__ float d_D1p[NB * C * MP];                                // fp32 fallback
__device__ float d_D2p[NB * C * MP];
__device__ float d_vm[NB * MP];
__device__ float d_partA[NB * GB];
__device__ float d_partB[NPOSB];

// ---------------------------------------------------------------------------
// Helpers
// ---------------------------------------------------------------------------
__device__ __forceinline__ uint32_t smem_u32(const void* p) {
    uint32_t a;
    asm("{ .reg .u64 t; cvta.to.shared.u64 t, %1; cvt.u32.u64 %0, t; }" : "=r"(a) : "l"(p));
    return a;
}

#if HAS_TC
__device__ __forceinline__ uint32_t elect_one() {
    uint32_t p;
    asm volatile("{ .reg .pred p; elect.sync _|p, 0xFFFFFFFF; selp.b32 %0, 1, 0, p; }" : "=r"(p));
    return p;
}
static __device__ __forceinline__ uint64_t make_desc(uint32_t addr) {
    // SW128, version=1(Blackwell), SBO=64, LBO=1
    const uint64_t base = (uint64_t(2) << 61) | (uint64_t(1) << 46)
                        | (uint64_t(64) << 32) | (uint64_t(1) << 16);
    return base | ((uint64_t)(addr >> 4) & 0x3FFF);
}
__device__ __forceinline__ void mma_f16_ss_cg1(uint32_t d_tmem, uint64_t a_desc,
                                               uint64_t b_desc, uint32_t idesc,
                                               uint32_t enable) {
    asm volatile(
        "{\n\t.reg .pred p;\n\t"
        "setp.ne.u32 p, %4, 0;\n\t"
        "tcgen05.mma.cta_group::1.kind::f16 [%0], %1, %2, %3, {%5, %5, %5, %5}, p;\n\t}"
        :: "r"(d_tmem), "l"(a_desc), "l"(b_desc), "r"(idesc), "r"(enable), "r"(0u)
        : "memory");
}
__device__ __forceinline__ void mbar_wait(uint32_t mbar, uint32_t parity) {
    uint32_t done;
    asm volatile(
        "{\n\t.reg .pred p;\n\t"
        "mbarrier.try_wait.parity.acquire.cta.shared::cta.b64 p, [%1], %2;\n\t"
        "selp.b32 %0, 1, 0, p;\n\t}"
        : "=r"(done) : "r"(mbar), "r"(parity) : "memory");
    if (!done) {
        asm volatile(
            "{\n\t.reg .pred P1;\n\t"
            "WL_%=:\n\t"
            "mbarrier.try_wait.parity.acquire.cta.shared::cta.b64 P1, [%0], %1, 0x989680;\n\t"
            "@P1 bra.uni WD_%=;\n\t"
            "bra.uni WL_%=;\n\t"
            "WD_%=:\n\t}"
            :: "r"(mbar), "r"(parity) : "memory");
    }
}
__device__ __forceinline__ void mbar_arrive(uint32_t mbar) {
    asm volatile("mbarrier.arrive.release.cta.shared::cta.b64 _, [%0];"
                 :: "r"(mbar) : "memory");
}
__device__ __forceinline__ void mbar_expect_tx(uint32_t mbar, uint32_t bytes) {
    asm volatile("mbarrier.arrive.expect_tx.shared.b64 _, [%0], %1;"
                 :: "r"(mbar), "r"(bytes) : "memory");
}
__device__ __forceinline__ void tma3d(uint32_t dst, const CUtensorMap* tmap,
                                      int x, int y, int z, uint32_t mbar) {
    asm volatile(
        "cp.async.bulk.tensor.3d.shared::cta.global.tile.mbarrier::complete_tx::bytes "
        "[%0], [%1, {%2, %3, %4}], [%5];"
        :: "r"(dst), "l"((uint64_t)tmap), "r"(x), "r"(y), "r"(z), "r"(mbar)
        : "memory");
}

#define LDTM_X32(dr, addr)                                                     \
    asm volatile(                                                              \
        "tcgen05.ld.sync.aligned.32x32b.x32.b32 "                              \
        "{%0, %1, %2, %3, %4, %5, %6, %7, "                                    \
        " %8, %9, %10, %11, %12, %13, %14, %15, "                              \
        " %16, %17, %18, %19, %20, %21, %22, %23, "                            \
        " %24, %25, %26, %27, %28, %29, %30, %31}, [%32];"                     \
        : "=r"((dr)[0]),  "=r"((dr)[1]),  "=r"((dr)[2]),  "=r"((dr)[3]),       \
          "=r"((dr)[4]),  "=r"((dr)[5]),  "=r"((dr)[6]),  "=r"((dr)[7]),       \
          "=r"((dr)[8]),  "=r"((dr)[9]),  "=r"((dr)[10]), "=r"((dr)[11]),      \
          "=r"((dr)[12]), "=r"((dr)[13]), "=r"((dr)[14]), "=r"((dr)[15]),      \
          "=r"((dr)[16]), "=r"((dr)[17]), "=r"((dr)[18]), "=r"((dr)[19]),      \
          "=r"((dr)[20]), "=r"((dr)[21]), "=r"((dr)[22]), "=r"((dr)[23]),      \
          "=r"((dr)[24]), "=r"((dr)[25]), "=r"((dr)[26]), "=r"((dr)[27]),      \
          "=r"((dr)[28]), "=r"((dr)[29]), "=r"((dr)[30]), "=r"((dr)[31])       \
        : "r"(addr))

// Epilogue: this warp reads 64 columns [c0, c0+64) of its 32-lane
// subpartition. Hinge via max(d, 0.2); constant part folded out at the end.
__device__ __forceinline__ void epi64(uint32_t tsrc, const float* vmv, float& local) {
    uint32_t dr[64];
    LDTM_X32(dr,      tsrc);
    LDTM_X32(dr + 32, tsrc + 32);
    asm volatile("tcgen05.wait::ld.sync.aligned;" ::: "memory");
    float a0 = 0.f, a1 = 0.f, a2 = 0.f, a3 = 0.f;
    #pragma unroll
    for (int k = 0; k < 64; k += 4) {
        a0 = fmaf(vmv[k + 0], fmaxf(__uint_as_float(dr[k + 0]), 0.2f), a0);
        a1 = fmaf(vmv[k + 1], fmaxf(__uint_as_float(dr[k + 1]), 0.2f), a1);
        a2 = fmaf(vmv[k + 2], fmaxf(__uint_as_float(dr[k + 2]), 0.2f), a2);
        a3 = fmaf(vmv[k + 3], fmaxf(__uint_as_float(dr[k + 3]), 0.2f), a3);
    }
    local += (a0 + a1) + (a2 + a3);
}
#endif

// ---------------------------------------------------------------------------
// Transpose + pad + bf16 convert: [n][c][m] f32 -> [n][m][c] bf16.
// 64-wide c-tiles so the bf16 write phase issues full 128B/warp transactions.
// Non-"a" targets also write padded fp32 copies for the SIMT fallback.
// ---------------------------------------------------------------------------
__global__ void transpose_kernel(const float* __restrict__ d1,
                                 const float* __restrict__ d2) {
    __shared__ float t1[64][33];
    __shared__ float t2[64][33];
    int m0 = blockIdx.x * 32, c0 = blockIdx.y * 64, n = blockIdx.z;
    int tx = threadIdx.x, ty = threadIdx.y;   // 32 x 8

    #pragma unroll
    for (int i = 0; i < 8; i++) {
        int c = c0 + ty + i * 8, m = m0 + tx;
        float v1 = 0.f, v2 = 0.f;
        if (m < M) {
            size_t idx = ((size_t)n * C + c) * M + m;
            v1 = d1[idx]; v2 = d2[idx];
        }
        t1[ty + i * 8][tx] = v1;
        t2[ty + i * 8][tx] = v2;
#if !HAS_TC
        size_t o = ((size_t)n * C + c) * MP + m;
        d_D1p[o] = v1;
        d_D2p[o] = v2;
#endif
    }
    __syncthreads();
    #pragma unroll
    for (int i = 0; i < 4; i++) {
        int m = m0 + ty + i * 8;          // always < MP (m0 <= 3680)
        int c = c0 + tx * 2;
        size_t o = ((size_t)n * MP + m) * C + c;
        __nv_bfloat162 b1, b2;
        b1.x = __float2bfloat16(t1[tx * 2][ty + i * 8]);
        b1.y = __float2bfloat16(t1[tx * 2 + 1][ty + i * 8]);
        b2.x = __float2bfloat16(t2[tx * 2][ty + i * 8]);
        b2.y = __float2bfloat16(t2[tx * 2 + 1][ty + i * 8]);
        *(__nv_bfloat162*)(d_D1t + o) = b1;
        *(__nv_bfloat162*)(d_D2t + o) = b2;
    }
}

// ---------------------------------------------------------------------------
// vm[n, i, j] = prod of 8x8 block of vis_mask1; padded entries are 0.
// ---------------------------------------------------------------------------
__global__ void vm_kernel(const float* __restrict__ vis) {
    int idx = blockIdx.x * blockDim.x + threadIdx.x;
    if (idx >= NB * MP) return;
    int mp = idx % MP;
    int n  = idx / MP;
    float p = 0.f;
    if (mp < M) {
        int i = mp / WR, j = mp % WR;
        p = 1.f;
        const float* base = vis + n * HH * WW + (i * GS) * WW + j * GS;
        #pragma unroll
        for (int a = 0; a < GS; a++)
            #pragma unroll
            for (int b = 0; b < GS; b++)
                p *= base[a * WW + b];
    }
    d_vm[idx] = p;
}

// ---------------------------------------------------------------------------
// 3-role warp-specialized persistent-strip tcgen05 GEMM (R13 structure,
// proven). Grid (29, 1, 4), 320 threads:
//   warps 0-7: pure epilogue (LDTM + hinge + reduce)
//   warp  8  : pure MMA (wait load -> 8 MMAs/half -> commit)
//   warp  9  : pure TMA producer (wait slot exec done -> TMA next half)
// B strip (full K, 64KB) TMA'd once; A streamed as K=128 half-tiles through
// a 4-slot ring (32KB). Slot s receives halves h === s (mod 4); tile
// completion = odd-half commit on slot 1/3 (clean parity).
// mbarriers: load[4] (cnt1+tx32KB), half[4] (cnt1, commit), epi[2] (cnt256),
//            B (cnt1+tx64KB).
// ---------------------------------------------------------------------------
__global__ __launch_bounds__(320, 1) void gemm_tc_kernel(
    const __grid_constant__ CUtensorMap tmapA,
    const __grid_constant__ CUtensorMap tmapB) {
#if HAS_TC
    extern __shared__ char dyn_sm[];
    __shared__ uint32_t s_tmem[1];
    __shared__ __align__(8) unsigned long long s_mbar[11]; // load[4] half[4] epi[2] B
    __shared__ float s_red[8];

    const int n   = blockIdx.z;
    const int xs  = blockIdx.x;
    const int tid = threadIdx.x;
    const int wid = tid >> 5, lid = tid & 31;

    uint32_t raw  = smem_u32(dyn_sm);
    uint32_t base = (raw + 1023u) & ~1023u;

    if (wid == 8) {
        asm volatile("tcgen05.alloc.cta_group::1.sync.aligned.shared::cta.b32 [%0], %1;"
                     :: "r"(smem_u32(s_tmem)), "r"(256u) : "memory");
        asm volatile("tcgen05.relinquish_alloc_permit.cta_group::1.sync.aligned;");
    }
    if (tid == 0) {
        #pragma unroll
        for (int k = 0; k < 8; k++)   // load[4], half[4]: count 1
            asm volatile("mbarrier.init.shared.b64 [%0], %1;"
                         :: "r"(smem_u32(&s_mbar[k])), "r"(1u) : "memory");
        #pragma unroll
        for (int k = 8; k < 10; k++)  // epi[2]: count 256
            asm volatile("mbarrier.init.shared.b64 [%0], %1;"
                         :: "r"(smem_u32(&s_mbar[k])), "r"(256u) : "memory");
        asm volatile("mbarrier.init.shared.b64 [%0], %1;"
                     :: "r"(smem_u32(&s_mbar[10])), "r"(1u) : "memory");   // B
    }
    __syncthreads();
    const uint32_t tmem = s_tmem[0];
    uint32_t mb_load[4], mb_half[4], mb_epi[2], mb_B;
    #pragma unroll
    for (int k = 0; k < 4; k++) { mb_load[k] = smem_u32(&s_mbar[k]); mb_half[k] = smem_u32(&s_mbar[4 + k]); }
    mb_epi[0] = smem_u32(&s_mbar[8]); mb_epi[1] = smem_u32(&s_mbar[9]);
    mb_B = smem_u32(&s_mbar[10]);

    if (wid < 8) {
        // ---------------- pure epilogue warps (256 threads) ----------------
        const int c0 = (wid >= 4) ? 64 : 0;
        float vmv[64];
        float sum_vm = 0.f;
        {
            const float* vmb = d_vm + n * MP + xs * BN + c0;
            #pragma unroll
            for (int k = 0; k < 64; k++) { vmv[k] = vmb[k]; sum_vm += vmb[k]; }
        }

        float local = 0.f;
        #pragma unroll 1
        for (int tt = 0; tt < NT; tt++) {
            const int s = (tt & 1) ? 3 : 1;           // slot of odd half 2tt+1
            mbar_wait(mb_half[s], (uint32_t)((tt >> 1) & 1));
            asm volatile("tcgen05.fence::after_thread_sync;" ::: "memory");
            epi64(tmem + (tt & 1) * 128 + c0, vmv, local);
            mbar_arrive(mb_epi[tt & 1]);              // tmem[tt&1] consumed
        }

        local -= 0.2f * (float)NT * sum_vm;           // fold out hinge constant

        #pragma unroll
        for (int o = 16; o > 0; o >>= 1)
            local += __shfl_down_sync(0xffffffffu, local, o);
        if (lid == 0) s_red[wid] = local;
    } else if (wid == 8) {
        // ---------------- pure MMA warp ----------------
        const bool leader = elect_one() != 0;
        int pl[4] = {0, 0, 0, 0};
        int pe[2] = {0, 0};

        mbar_wait(mb_B, 0u);                          // B resident

        #pragma unroll 1
        for (int h = 0; h < NH; h++) {
            const int s = h & 3, t = h >> 1;
            mbar_wait(mb_load[s], (uint32_t)(pl[s] & 1));
            pl[s]++;
            if (!(h & 1) && t >= 2) {                 // tmem[t&1] free of t-2 reads
                mbar_wait(mb_epi[t & 1], (uint32_t)(pe[t & 1] & 1));
                pe[t & 1]++;
            }
            if (leader) {
                const uint32_t dt = tmem + (t & 1) * 128;
                #pragma unroll
                for (int cc = 0; cc < 2; cc++) {
                    uint64_t ad = make_desc(base + A_SLOT(s) + cc * 16384u);
                    uint64_t bd = make_desc(base + B_OFF + ((h & 1) * 2 + cc) * 16384u);
                    #pragma unroll
                    for (int ks = 0; ks < 4; ks++)
                        mma_f16_ss_cg1(dt, ad + ks * 2, bd + ks * 2, MMA_IDESC,
                                       (uint32_t)((h & 1) | cc | ks));
                }
                asm volatile(
                    "tcgen05.commit.cta_group::1.mbarrier::arrive::one.shared::cluster.b64 [%0];"
                    :: "r"(mb_half[s]) : "memory");
            }
        }
    } else {
        // ---------------- pure TMA producer warp ----------------
        const bool leader = elect_one() != 0;

        // TMA half h (2 chunks of 64 cols = 32KB) into slot h&3
        auto tma_half = [&](int h) {
            const int s = h & 3, t = h >> 1, ko = (h & 1) * 128;
            mbar_expect_tx(mb_load[s], 32768u);
            tma3d(base + A_SLOT(s),          &tmapA, ko,      t * 128, n, mb_load[s]);
            tma3d(base + A_SLOT(s) + 16384u, &tmapA, ko + 64, t * 128, n, mb_load[s]);
        };

        if (leader) {
            mbar_expect_tx(mb_B, 65536u);
            #pragma unroll
            for (int cc = 0; cc < 4; cc++)
                tma3d(base + B_OFF + cc * 16384u, &tmapB, cc * 64, xs * 128, n, mb_B);
            tma_half(0);
            tma_half(1);
            tma_half(2);
            tma_half(3);
        }

        int ph[4] = {0, 0, 0, 0};
        #pragma unroll 1
        for (int h = 4; h < NH; h++) {
            const int s = h & 3;
            mbar_wait(mb_half[s], (uint32_t)(ph[s] & 1));   // exec of h-4 done
            ph[s]++;
            if (leader) tma_half(h);
        }
    }

    __syncthreads();
    if (tid == 0) {
        float t = 0.f;
        #pragma unroll
        for (int w = 0; w < 8; w++) t += s_red[w];
        d_partA[n * GB + xs] = t;
    }
    if (wid == 8) {
        asm volatile("tcgen05.dealloc.cta_group::1.sync.aligned.b32 %0, %1;"
                     :: "r"(tmem), "r"(256u));
    }
#endif
}

// ---------------------------------------------------------------------------
// Fallback SIMT fp32 GEMM, persistent strips (launched only when the device
// lacks tcgen05). Grid (29, 1, 4).
// ---------------------------------------------------------------------------
__global__ __launch_bounds__(256, 1) void gemm_simt_kernel() {
#if !HAS_TC
    int n = blockIdx.z, xs = blockIdx.x;
    const float* Bb = d_D2p + n * C * MP + xs * BN;

    __shared__ float As[2][BK][BM];
    __shared__ float Bs[2][BK][BN];

    int tid  = threadIdx.x;
    int tx   = tid & 15;
    int ty2  = tid >> 4;
    int lrow = tid >> 5;
    int lcol = (tid & 31) << 2;

    float vmv[8];
    #pragma unroll
    for (int j = 0; j < 8; j++)
        vmv[j] = d_vm[n * MP + xs * BN + tx * 8 + j];

    float total = 0.f;

    #pragma unroll 1
    for (int ty = 0; ty < GB; ty++) {
        const float* Ab = d_D1p + n * C * MP + ty * BM;

        float acc[8][8];
        #pragma unroll
        for (int i = 0; i < 8; i++)
            #pragma unroll
            for (int j = 0; j < 8; j++) acc[i][j] = 0.f;

        *(float4*)&As[0][lrow][lcol] = *(const float4*)&Ab[lrow * MP + lcol];
        *(float4*)&Bs[0][lrow][lcol] = *(const float4*)&Bb[lrow * MP + lcol];
        __syncthreads();

        #pragma unroll 1
        for (int k0 = 0; k0 < C; k0 += BK) {
            int buf = (k0 >> 3) & 1;
            if (k0 + BK < C) {
                *(float4*)&As[buf ^ 1][lrow][lcol] =
                    *(const float4*)&Ab[(k0 + BK + lrow) * MP + lcol];
                *(float4*)&Bs[buf ^ 1][lrow][lcol] =
                    *(const float4*)&Bb[(k0 + BK + lrow) * MP + lcol];
            }
            #pragma unroll
            for (int kk = 0; kk < BK; kk++) {
                float a[8], b[8];
                *(float4*)&a[0] = *(const float4*)&As[buf][kk][ty2 * 8];
                *(float4*)&a[4] = *(const float4*)&As[buf][kk][ty2 * 8 + 4];
                *(float4*)&b[0] = *(const float4*)&Bs[buf][kk][tx * 8];
                *(float4*)&b[4] = *(const float4*)&Bs[buf][kk][tx * 8 + 4];
                #pragma unroll
                for (int i = 0; i < 8; i++)
                    #pragma unroll
                    for (int j = 0; j < 8; j++)
                        acc[i][j] = fmaf(a[i], b[j], acc[i][j]);
            }
            __syncthreads();
        }

        #pragma unroll
        for (int i = 0; i < 8; i++)
            #pragma unroll
            for (int j = 0; j < 8; j++)
                total += vmv[j] * fmaxf(acc[i][j] - 0.2f, 0.f);
    }

    #pragma unroll
    for (int o = 16; o > 0; o >>= 1)
        total += __shfl_down_sync(0xffffffffu, total, o);

    __shared__ float wsum[8];
    if ((tid & 31) == 0) wsum[tid >> 5] = total;
    __syncthreads();
    if (tid == 0) {
        float t = 0.f;
        #pragma unroll
        for (int w = 0; w < 8; w++) t += wsum[w];
        d_partA[n * GB + xs] = t;
    }
#endif
}

// ---------------------------------------------------------------------------
// Positive-pair correction: 4 items per warp via 8-lane groups; exact 2x2
// candidate window. All intra-group shuffles use the GROUP mask (0xFF<<g*8):
// branches diverge BETWEEN groups, so a full-warp mask would deadlock
// (the R14/R15 hang). Within a group the predicate is uniform.
// ---------------------------------------------------------------------------
__device__ __forceinline__ float dot8(uint4 a, uint4 b) {
    const __nv_bfloat162* pa = (const __nv_bfloat162*)&a;
    const __nv_bfloat162* pb = (const __nv_bfloat162*)&b;
    float s = 0.f;
    #pragma unroll
    for (int k = 0; k < 4; k++) {
        float2 fa = __bfloat1622float2(pa[k]);
        float2 fb = __bfloat1622float2(pb[k]);
        s += fa.x * fb.x + fa.y * fb.y;
    }
    return s;
}

__global__ void pos_kernel(const float* __restrict__ homo) {
    const int warp = threadIdx.x >> 5;
    const int lane = threadIdx.x & 31;
    const int g    = lane >> 3;          // 8-lane group 0..3
    const int li   = lane & 7;
    const uint32_t gmask = 0xFFu << (g * 8);
    const int item = (blockIdx.x * 8 + warp) * 4 + g;   // 0 .. 14399
    float contrib = 0.f;

    if (item < NB * M) {
        int n  = item / M;
        int ij = item % M;
        int i  = ij / WR, j = ij % WR;
        float x = j * 8 + 4.f, y = i * 8 + 4.f;
        const float* Hm = homo + n * 9;
        float wxh = Hm[0] * x + Hm[1] * y + Hm[2];
        float wyh = Hm[3] * x + Hm[4] * y + Hm[5];
        float wzh = Hm[6] * x + Hm[7] * y + Hm[8];
        float wx = wxh / wzh, wy = wyh / wzh;
        float vmv = d_vm[n * MP + ij];

        const uint4* brow = (const uint4*)(d_D2t + ((size_t)n * MP + ij) * C);
        const uint4 b0 = brow[li], b1 = brow[li + 8], b2 = brow[li + 16], b3 = brow[li + 24];

        // first candidate row/col: cells below ceil((w-11.5)/8) are >7.5 away
        const int h0 = (int)ceilf((wy - 11.5f) * 0.125f);
        const int w0 = (int)ceilf((wx - 11.5f) * 0.125f);
        #pragma unroll
        for (int a = 0; a < 2; a++) {
            int hh = h0 + a;
            if (hh < 0 || hh >= HR) continue;
            float dy = hh * 8 + 4.f - wy;
            #pragma unroll
            for (int b = 0; b < 2; b++) {
                int wc = w0 + b;
                if (wc < 0 || wc >= WR) continue;
                float dx = wc * 8 + 4.f - wx;
                if (dx * dx + dy * dy <= 56.25f) {   // dist <= 7.5 (group-uniform)
                    const uint4* arow =
                        (const uint4*)(d_D1t + ((size_t)n * MP + hh * WR + wc) * C);
                    float dt = dot8(arow[li], b0) + dot8(arow[li + 8], b1)
                             + dot8(arow[li + 16], b2) + dot8(arow[li + 24], b3);
                    dt += __shfl_xor_sync(gmask, dt, 4);
                    dt += __shfl_xor_sync(gmask, dt, 2);
                    dt += __shfl_xor_sync(gmask, dt, 1);
                    if (li == 0)
                        contrib += vmv * (fmaxf(1.f - dt, 0.f) - fmaxf(dt - 0.2f, 0.f));
                }
            }
        }
    }

    // combine the 4 group leaders (all 32 lanes converged here; full mask legal)
    contrib += __shfl_xor_sync(0xffffffffu, contrib, 8);
    contrib += __shfl_xor_sync(0xffffffffu, contrib, 16);

    __shared__ float wsh[8];
    if (lane == 0) wsh[warp] = contrib;
    __syncthreads();
    if (threadIdx.x == 0) {
        float t = 0.f;
        #pragma unroll
        for (int w = 0; w < 8; w++) t += wsh[w];
        d_partB[blockIdx.x] = t;
    }
}

// ---------------------------------------------------------------------------
// Final deterministic reduction (116 strip partials on both paths).
// ---------------------------------------------------------------------------
__global__ void final_kernel(float* __restrict__ out) {
    __shared__ float sh[256];
    int tid = threadIdx.x;

    float s = 0.f;
    for (int k = tid; k < NB * GB; k += 256) s += d_partA[k];
    for (int k = tid; k < NPOSB; k += 256) s += d_partB[k];
    float v = 0.f;
    for (int k = tid; k < NB * MP; k += 256) v += d_vm[k];  // pads are 0

    sh[tid] = s;
    __syncthreads();
    for (int o = 128; o > 0; o >>= 1) {
        if (tid < o) sh[tid] += sh[tid + o];
        __syncthreads();
    }
    float total = sh[0];
    __syncthreads();

    sh[tid] = v;
    __syncthreads();
    for (int o = 128; o > 0; o >>= 1) {
        if (tid < o) sh[tid] += sh[tid + o];
        __syncthreads();
    }
    if (tid == 0)
        out[0] = total / (3600.f * sh[0]);   // LOSS_LAMBDA = 1
}

// ---------------------------------------------------------------------------
// Host: tensormap construction via driver entry point (no -lcuda needed).
// ---------------------------------------------------------------------------
typedef CUresult (*PFN_encodeTiled)(
    CUtensorMap*, CUtensorMapDataType, cuuint32_t, void*,
    const cuuint64_t*, const cuuint64_t*, const cuuint32_t*, const cuuint32_t*,
    CUtensorMapInterleave, CUtensorMapSwizzle, CUtensorMapL2promotion,
    CUtensorMapFloatOOBfill);

static void build_tmap(PFN_encodeTiled enc, CUtensorMap* tm, void* gptr) {
    cuuint64_t dims[3]    = {C, MP, NB};
    cuuint64_t strides[2] = {(cuuint64_t)C * 2, (cuuint64_t)MP * C * 2};
    cuuint32_t box[3]     = {64, 128, 1};
    cuuint32_t es[3]      = {1, 1, 1};
    enc(tm, CU_TENSOR_MAP_DATA_TYPE_BFLOAT16, 3, gptr, dims, strides, box, es,
        CU_TENSOR_MAP_INTERLEAVE_NONE, CU_TENSOR_MAP_SWIZZLE_128B,
        CU_TENSOR_MAP_L2_PROMOTION_L2_128B, CU_TENSOR_MAP_FLOAT_OOB_FILL_NONE);
}

extern "C" void kernel_launch(void* const* d_in, const int* in_sizes, int n_in,
                              void* d_out, int out_size) {
    const float* desc1 = nullptr;
    const float* desc2 = nullptr;
    const float* homo  = nullptr;
    const float* vis   = nullptr;
    for (int k = 0; k < n_in; k++) {
        if (in_sizes[k] == NB * C * M) {
            if (!desc1) desc1 = (const float*)d_in[k];
            else if (!desc2) desc2 = (const float*)d_in[k];
        } else if (in_sizes[k] == NB * 9) {
            homo = (const float*)d_in[k];
        } else if (in_sizes[k] == NB * HH * WW) {
            vis = (const float*)d_in[k];
        }
    }

    // Device gate: sm_10x has tcgen05; pick ONE gemm path.
    int dev = 0, cc_major = 0;
    cudaGetDevice(&dev);
    cudaDeviceGetAttribute(&cc_major, cudaDevAttrComputeCapabilityMajor, dev);
    const bool use_tc = (cc_major >= 10);

    // tensormaps for the GEMM TMA loads (host-side only; baked into the graph)
    CUtensorMap tA, tB;
    if (use_tc) {
        void* fn = nullptr;
        cudaDriverEntryPointQueryResult qr;
#if CUDART_VERSION >= 12050
        cudaGetDriverEntryPointByVersion("cuTensorMapEncodeTiled", &fn, 12000,
                                         cudaEnableDefault, &qr);
#else
        cudaGetDriverEntryPoint("cuTensorMapEncodeTiled", &fn,
                                cudaEnableDefault, &qr);
#endif
        void* pA = nullptr; void* pB = nullptr;
        cudaGetSymbolAddress(&pA, d_D1t);
        cudaGetSymbolAddress(&pB, d_D2t);
        if (fn) {
            build_tmap((PFN_encodeTiled)fn, &tA, pA);
            build_tmap((PFN_encodeTiled)fn, &tB, pB);
        }
        cudaFuncSetAttribute(gemm_tc_kernel,
                             cudaFuncAttributeMaxDynamicSharedMemorySize, 197632);
    }

    transpose_kernel<<<dim3(116, 4, NB), dim3(32, 8)>>>(desc1, desc2);
    vm_kernel<<<(NB * MP + 255) / 256, 256>>>(vis);
    if (use_tc)
        gemm_tc_kernel<<<dim3(GB, 1, NB), 320, 197632>>>(tA, tB);
    else
        gemm_simt_kernel<<<dim3(GB, 1, NB), 256>>>();
    pos_kernel<<<NPOSB, 256>>>(homo);
    final_kernel<<<1, 256>>>((float*)d_out);
}